// round 7
// baseline (speedup 1.0000x reference)
#include <cuda_runtime.h>
#include <cuda_bf16.h>
#include <math.h>

#define NG 20000
#define NP 100000
#define NM 5000
#define NTOT (NG + NP + NM)
#define HID 64
#define NLAYERS 2
#define EMAX 1000000
#define FULL 0xFFFFFFFFu

// ---------------- scratch (static device globals; no allocs) ----------------
__device__ float g_h [NTOT * HID];       // packed [gene | patient | group]
__device__ float g_hn[NTOT * HID];
__device__ int   g_cnt[4][NP];           // per-type dst counts
__device__ int   g_off[4][NP + 1];       // CSR offsets
__device__ int   g_cur[4][NP + 1];       // fill cursors
__device__ int   g_col[4][EMAX];         // CSR column (src) indices

#define OFF_GENE 0
#define OFF_PAT  (NG * HID)
#define OFF_GRP  ((NG + NP) * HID)

__device__ __forceinline__ float elu1(float x) { return x > 0.f ? x : expm1f(x); }

// ---------------- utility kernels ----------------
__global__ void zero_int_kernel(int* p, int n) {
    int i = blockIdx.x * blockDim.x + threadIdx.x;
    int stride = gridDim.x * blockDim.x;
    for (; i < n; i += stride) p[i] = 0;
}

__global__ void copy_int_kernel(int* dst, const int* src, int n) {
    int i = blockIdx.x * blockDim.x + threadIdx.x;
    int stride = gridDim.x * blockDim.x;
    for (; i < n; i += stride) dst[i] = src[i];
}

// encoder: h[n,j] = elu(b[j] + sum_k x[n,k] * W[k,j])
template <int K>
__global__ void encoder_kernel(const float* __restrict__ x,
                               const float* __restrict__ W,
                               const float* __restrict__ b,
                               float* __restrict__ h, int N) {
    int idx = blockIdx.x * blockDim.x + threadIdx.x;
    if (idx >= N * HID) return;
    int n = idx >> 6;
    int j = idx & 63;
    float acc = b[j];
#pragma unroll
    for (int k = 0; k < K; k++)
        acc += x[n * K + k] * W[k * HID + j];
    h[idx] = elu1(acc);
}

// ---------------- CSR build ----------------
__global__ void count_kernel(const int* __restrict__ dst, int E, int* __restrict__ cnt) {
    int i = blockIdx.x * blockDim.x + threadIdx.x;
    if (i < E) atomicAdd(&cnt[dst[i]], 1);
}

// one block per edge type; exclusive scan of counts into offsets
__global__ void scan4_kernel(const int* __restrict__ cnt_base, int* __restrict__ off_base, int E) {
    const int Ns[4] = { NP, NG, NM, NG };
    int t = blockIdx.x;
    const int* cnt = cnt_base + t * NP;
    int* off = off_base + t * (NP + 1);
    int N = Ns[t];

    __shared__ int wsum[32];
    __shared__ int carry_s;
    if (threadIdx.x == 0) carry_s = 0;
    __syncthreads();
    int lane = threadIdx.x & 31, wid = threadIdx.x >> 5;
    int nw = blockDim.x >> 5;

    for (int base = 0; base < N; base += blockDim.x) {
        int i = base + threadIdx.x;
        int v = (i < N) ? cnt[i] : 0;
        int x = v;
#pragma unroll
        for (int o = 1; o < 32; o <<= 1) { int tt = __shfl_up_sync(FULL, x, o); if (lane >= o) x += tt; }
        if (lane == 31) wsum[wid] = x;
        __syncthreads();
        if (wid == 0) {
            int w = (lane < nw) ? wsum[lane] : 0;
#pragma unroll
            for (int o = 1; o < 32; o <<= 1) { int tt = __shfl_up_sync(FULL, w, o); if (lane >= o) w += tt; }
            wsum[lane] = w;
        }
        __syncthreads();
        int incl = x + (wid > 0 ? wsum[wid - 1] : 0);
        int carry = carry_s;
        if (i < N) off[i] = carry + incl - v;       // exclusive
        __syncthreads();
        if (threadIdx.x == blockDim.x - 1) carry_s = carry + incl;
        __syncthreads();
    }
    if (threadIdx.x == 0) off[N] = E;
}

__global__ void fill_kernel(const int* __restrict__ src, const int* __restrict__ dst,
                            int E, int* __restrict__ cur, int* __restrict__ col) {
    int i = blockIdx.x * blockDim.x + threadIdx.x;
    if (i < E) {
        int p = atomicAdd(&cur[dst[i]], 1);
        col[p] = src[i];
    }
}

// ---------------- fused pull (mean) + SAGE linear ----------------
// Block = 256 threads handles a 64-node tile:
//   phase 1: 8 warps pull 8 nodes each (float4 gather, two edges per warp-step)
//            directly into smem sA; root rows staged into sR.
//   phase 2: 64x64x64 dual-matrix GEMM with 4x4 register blocking.
// dynamic smem: sWl[4096] | sWr[4096] | sA[4096] | sR[4096]  (64 KB)
__global__ void pull_sage_kernel(const float* __restrict__ h_src,
                                 const int* __restrict__ off,
                                 const int* __restrict__ col,
                                 const float* __restrict__ h_root,
                                 const float* __restrict__ Wl,
                                 const float* __restrict__ bl,
                                 const float* __restrict__ Wr,
                                 float* __restrict__ hn, int N, int accum) {
    extern __shared__ float sm[];
    float* sWl = sm;
    float* sWr = sm + 4096;
    float* sA  = sm + 8192;
    float* sR  = sm + 12288;

    for (int i = threadIdx.x; i < 4096; i += 256) {
        sWl[i] = Wl[i];
        sWr[i] = Wr[i];
    }
    const int tx = threadIdx.x & 15;   // GEMM col group: j0 = tx*4
    const int ty = threadIdx.x >> 4;   // GEMM node group: nb = ty*4
    const int j0 = tx * 4;
    const int nb = ty * 4;
    const float4 bias = *(const float4*)(bl + j0);
    const int w    = threadIdx.x >> 5; // warp 0..7
    const int lane = threadIdx.x & 31;
    const int half = lane >> 4;        // 0 or 1
    const int q    = lane & 15;        // float4 index within row
    __syncthreads();

    for (int n0 = blockIdx.x * 64; n0 < N; n0 += gridDim.x * 64) {
        // ---- phase 1: pull 8 nodes per warp into sA, stage roots into sR ----
        for (int i = 0; i < 8; i++) {
            int row = w * 8 + i;
            int n = n0 + row;
            float4 acc = make_float4(0.f, 0.f, 0.f, 0.f);
            int degc = 0;
            if (n < N) {
                // stage root row: half-warp 1 (16 lanes x 16B = full 256B row)
                if (half)
                    *(float4*)&sR[row * 64 + q * 4] =
                        ((const float4*)(h_root + (size_t)n * HID))[q];
                int o0 = off[n], o1 = off[n + 1];
                degc = o1 - o0;
                for (int base = o0; base < o1; base += 32) {
                    int idx = (base + lane < o1) ? col[base + lane] : 0;
                    int m = min(32, o1 - base);
                    // uniform trip count; halves take alternating edges
                    for (int j = 0; j < m; j += 2) {
                        int jj = j + half;
                        int s = __shfl_sync(FULL, idx, jj & 31);
                        if (jj < m) {
                            float4 v = ((const float4*)(h_src + (size_t)s * HID))[q];
                            acc.x += v.x; acc.y += v.y; acc.z += v.z; acc.w += v.w;
                        }
                    }
                }
            }
            // combine the two halves
            acc.x += __shfl_xor_sync(FULL, acc.x, 16);
            acc.y += __shfl_xor_sync(FULL, acc.y, 16);
            acc.z += __shfl_xor_sync(FULL, acc.z, 16);
            acc.w += __shfl_xor_sync(FULL, acc.w, 16);
            if (n < N && half == 0) {
                float inv = 1.f / fmaxf((float)degc, 1.f);
                *(float4*)&sA[row * 64 + q * 4] =
                    make_float4(acc.x * inv, acc.y * inv, acc.z * inv, acc.w * inv);
            }
        }
        __syncthreads();

        // ---- phase 2: hn[tile] = sA @ Wl + bl + sR @ Wr ----
        float acc[4][4];
#pragma unroll
        for (int i = 0; i < 4; i++) {
            acc[i][0] = bias.x; acc[i][1] = bias.y; acc[i][2] = bias.z; acc[i][3] = bias.w;
        }
#pragma unroll 8
        for (int k = 0; k < 64; k++) {
            float4 wl = *(const float4*)&sWl[k * 64 + j0];
            float4 wr = *(const float4*)&sWr[k * 64 + j0];
#pragma unroll
            for (int i = 0; i < 4; i++) {
                float a = sA[(nb + i) * 64 + k];
                float r = sR[(nb + i) * 64 + k];
                acc[i][0] += a * wl.x + r * wr.x;
                acc[i][1] += a * wl.y + r * wr.y;
                acc[i][2] += a * wl.z + r * wr.z;
                acc[i][3] += a * wl.w + r * wr.w;
            }
        }
#pragma unroll
        for (int i = 0; i < 4; i++) {
            int n = n0 + nb + i;
            if (n < N) {
                float* o = hn + (size_t)n * HID + j0;
                if (accum) {
                    o[0] += acc[i][0]; o[1] += acc[i][1];
                    o[2] += acc[i][2]; o[3] += acc[i][3];
                } else {
                    *(float4*)o = make_float4(acc[i][0], acc[i][1], acc[i][2], acc[i][3]);
                }
            }
        }
        __syncthreads();   // protect sA/sR before next tile overwrite
    }
}

// ---------------- residual + layernorm + elu over ALL node types ----------------
__global__ void update_all_kernel(float* __restrict__ h,
                                  const float* __restrict__ hn,
                                  const float* __restrict__ lnG,   // [3,64] for this layer
                                  const float* __restrict__ lnB) {
    int warp = (blockIdx.x * blockDim.x + threadIdx.x) >> 5;
    int lane = threadIdx.x & 31;
    if (warp >= NTOT) return;
    int t = (warp < NG) ? 0 : (warp < NG + NP ? 1 : 2);
    const float* gamma = lnG + t * HID;
    const float* beta  = lnB + t * HID;
    size_t base = (size_t)warp * HID;
    float a = h[base + lane]      + hn[base + lane];
    float c = h[base + 32 + lane] + hn[base + 32 + lane];
    float s = a + c;
#pragma unroll
    for (int o = 16; o; o >>= 1) s += __shfl_xor_sync(FULL, s, o);
    float mean = s * (1.f / 64.f);
    float da = a - mean, dc = c - mean;
    float vs = da * da + dc * dc;
#pragma unroll
    for (int o = 16; o; o >>= 1) vs += __shfl_xor_sync(FULL, vs, o);
    float rstd = rsqrtf(vs * (1.f / 64.f) + 1e-5f);
    h[base + lane]      = elu1(da * rstd * gamma[lane]      + beta[lane]);
    h[base + 32 + lane] = elu1(dc * rstd * gamma[32 + lane] + beta[32 + lane]);
}

// ---------------- cox head: one warp per patient ----------------
__global__ void cox_kernel(const float* __restrict__ h,
                           const float* __restrict__ W1,
                           const float* __restrict__ b1,
                           const float* __restrict__ W2,
                           const float* __restrict__ b2,
                           float* __restrict__ out, int N) {
    __shared__ float sW1[HID * 32];
    __shared__ float sb1[32];
    __shared__ float sW2[32];
    __shared__ float sb2;
    for (int i = threadIdx.x; i < HID * 32; i += blockDim.x) sW1[i] = W1[i];
    if (threadIdx.x < 32) { sb1[threadIdx.x] = b1[threadIdx.x]; sW2[threadIdx.x] = W2[threadIdx.x]; }
    if (threadIdx.x == 0) sb2 = b2[0];
    __syncthreads();

    int warp = (blockIdx.x * blockDim.x + threadIdx.x) >> 5;
    int lane = threadIdx.x & 31;
    if (warp >= N) return;
    size_t base = (size_t)warp * HID;
    float a = h[base + lane];
    float c = h[base + 32 + lane];
    float z = sb1[lane];
#pragma unroll
    for (int k = 0; k < 32; k++) {
        float hk = __shfl_sync(FULL, a, k);
        z += hk * sW1[k * 32 + lane];
    }
#pragma unroll
    for (int k = 0; k < 32; k++) {
        float hk = __shfl_sync(FULL, c, k);
        z += hk * sW1[(k + 32) * 32 + lane];
    }
    z = elu1(z);
    float hz = z * sW2[lane];
#pragma unroll
    for (int o = 16; o; o >>= 1) hz += __shfl_xor_sync(FULL, hz, o);
    if (lane == 0) out[warp] = hz + sb2;
}

// ---------------- host launcher ----------------
static inline int cdiv(long long a, long long b) { return (int)((a + b - 1) / b); }

extern "C" void kernel_launch(void* const* d_in, const int* in_sizes, int n_in,
                              void* d_out, int out_size) {
    const float* x_gene = (const float*)d_in[0];
    const float* x_pat  = (const float*)d_in[1];
    const float* x_grp  = (const float*)d_in[2];
    const int* src[4] = { (const int*)d_in[3], (const int*)d_in[5],
                          (const int*)d_in[7], (const int*)d_in[9] };
    const int* dst[4] = { (const int*)d_in[4], (const int*)d_in[6],
                          (const int*)d_in[8], (const int*)d_in[10] };
    const float* encGW = (const float*)d_in[11];
    const float* encGb = (const float*)d_in[12];
    const float* encPW = (const float*)d_in[13];
    const float* encPb = (const float*)d_in[14];
    const float* encMW = (const float*)d_in[15];
    const float* encMb = (const float*)d_in[16];
    const float* convWl = (const float*)d_in[17];   // [2,4,64,64]
    const float* convbl = (const float*)d_in[18];   // [2,4,64]
    const float* convWr = (const float*)d_in[19];   // [2,4,64,64]
    const float* lnG = (const float*)d_in[20];      // [2,3,64]
    const float* lnB = (const float*)d_in[21];
    const float* coxW1 = (const float*)d_in[22];
    const float* coxb1 = (const float*)d_in[23];
    const float* coxW2 = (const float*)d_in[24];
    const float* coxb2 = (const float*)d_in[25];
    float* out = (float*)d_out;

    const int E = in_sizes[3];

    float *hbuf, *hnbuf;
    int *cntb, *offb, *curb, *colb;
    cudaGetSymbolAddress((void**)&hbuf,  g_h);
    cudaGetSymbolAddress((void**)&hnbuf, g_hn);
    cudaGetSymbolAddress((void**)&cntb,  g_cnt);
    cudaGetSymbolAddress((void**)&offb,  g_off);
    cudaGetSymbolAddress((void**)&curb,  g_cur);
    cudaGetSymbolAddress((void**)&colb,  g_col);

    float* h_gene  = hbuf  + OFF_GENE;
    float* h_pat   = hbuf  + OFF_PAT;
    float* h_grp   = hbuf  + OFF_GRP;

    // per edge type: src features, dst count, root features, hn dst, accumulate?
    const float* eh_src[4] = { h_gene, h_pat, h_gene, h_grp };
    int    Ndst[4]   = { NP, NG, NM, NG };
    float* hroot[4]  = { h_pat, h_gene, h_grp, h_gene };
    float* hnew[4]   = { hnbuf + OFF_PAT, hnbuf + OFF_GENE, hnbuf + OFF_GRP, hnbuf + OFF_GENE };
    int    accum[4]  = { 0, 0, 0, 1 };   // gene hn written by e1, accumulated by e3

    static const int LIN_SMEM = 4 * 4096 * (int)sizeof(float);   // 64 KB
    cudaFuncSetAttribute(pull_sage_kernel,
                         cudaFuncAttributeMaxDynamicSharedMemorySize, LIN_SMEM);

    // ---- encoders ----
    encoder_kernel<11><<<cdiv((long long)NG * HID, 256), 256>>>(x_gene, encGW, encGb, h_gene, NG);
    encoder_kernel<3> <<<cdiv((long long)NP * HID, 256), 256>>>(x_pat,  encPW, encPb, h_pat,  NP);
    encoder_kernel<4> <<<cdiv((long long)NM * HID, 256), 256>>>(x_grp,  encMW, encMb, h_grp,  NM);

    // ---- CSR build (topology fixed; reused by both layers) ----
    zero_int_kernel<<<256, 256>>>(cntb, 4 * NP);
    for (int e = 0; e < 4; e++)
        count_kernel<<<cdiv(E, 256), 256>>>(dst[e], E, cntb + e * NP);
    scan4_kernel<<<4, 1024>>>(cntb, offb, E);
    copy_int_kernel<<<256, 256>>>(curb, offb, 4 * (NP + 1));
    for (int e = 0; e < 4; e++)
        fill_kernel<<<cdiv(E, 256), 256>>>(src[e], dst[e], E, curb + e * (NP + 1), colb + (size_t)e * EMAX);

    // ---- layers ----
    for (int layer = 0; layer < NLAYERS; layer++) {
        for (int e = 0; e < 4; e++) {
            int N = Ndst[e];
            const float* Wl = convWl + ((size_t)layer * 4 + e) * HID * HID;
            const float* bl = convbl + ((size_t)layer * 4 + e) * HID;
            const float* Wr = convWr + ((size_t)layer * 4 + e) * HID * HID;
            int grid = min(cdiv(N, 64), 444);
            pull_sage_kernel<<<grid, 256, LIN_SMEM>>>(
                eh_src[e], offb + e * (NP + 1), colb + (size_t)e * EMAX,
                hroot[e], Wl, bl, Wr, hnew[e], N, accum[e]);
        }
        update_all_kernel<<<cdiv((long long)NTOT * 32, 256), 256>>>(
            hbuf, hnbuf, lnG + (size_t)layer * 3 * HID, lnB + (size_t)layer * 3 * HID);
    }

    // ---- cox head ----
    cox_kernel<<<cdiv((long long)NP * 32, 256), 256>>>(h_pat, coxW1, coxb1, coxW2, coxb2, out, NP);
}

// round 8
// speedup vs baseline: 1.7602x; 1.7602x over previous
#include <cuda_runtime.h>
#include <cuda_bf16.h>
#include <math.h>

#define NG 20000
#define NP 100000
#define NM 5000
#define NTOT (NG + NP + NM)
#define HID 64
#define NLAYERS 2
#define EMAX 1000000
#define FULL 0xFFFFFFFFu

// segment layout for agg/hn (per edge type dst rows): e0|e1|e2|e3
#define A0 0
#define A1 NP
#define A2 (NP + NG)
#define A3 (NP + NG + NM)
#define NSEG (NP + NG + NM + NG)

// tiles per type for the merged linear
#define T0 ((NP + 63) / 64)
#define T1 ((NG + 63) / 64)
#define T2 ((NM + 63) / 64)
#define T3 ((NG + 63) / 64)
#define TTOT (T0 + T1 + T2 + T3)

// ---------------- scratch (static device globals; no allocs) ----------------
__device__ float g_h  [NTOT * HID];      // packed [gene | patient | group]
__device__ float g_agg[NSEG * HID];      // per-edge-type aggregated means
__device__ float g_hn [NSEG * HID];      // per-edge-type linear outputs
__device__ int   g_cnt[4][NP];           // per-type dst counts
__device__ int   g_off[4][NP + 1];       // CSR offsets
__device__ int   g_cur[4][NP + 1];       // fill cursors
__device__ int   g_col[4][EMAX];         // CSR column (src) indices

#define OFF_GENE 0
#define OFF_PAT  (NG * HID)
#define OFF_GRP  ((NG + NP) * HID)

__device__ __forceinline__ float elu1(float x) { return x > 0.f ? x : expm1f(x); }

// ---------------- utility kernels ----------------
__global__ void zero_int_kernel(int* p, int n) {
    int i = blockIdx.x * blockDim.x + threadIdx.x;
    int stride = gridDim.x * blockDim.x;
    for (; i < n; i += stride) p[i] = 0;
}

__global__ void copy_int_kernel(int* dst, const int* src, int n) {
    int i = blockIdx.x * blockDim.x + threadIdx.x;
    int stride = gridDim.x * blockDim.x;
    for (; i < n; i += stride) dst[i] = src[i];
}

// encoder: h[n,j] = elu(b[j] + sum_k x[n,k] * W[k,j])
template <int K>
__global__ void encoder_kernel(const float* __restrict__ x,
                               const float* __restrict__ W,
                               const float* __restrict__ b,
                               float* __restrict__ h, int N) {
    int idx = blockIdx.x * blockDim.x + threadIdx.x;
    if (idx >= N * HID) return;
    int n = idx >> 6;
    int j = idx & 63;
    float acc = b[j];
#pragma unroll
    for (int k = 0; k < K; k++)
        acc += x[n * K + k] * W[k * HID + j];
    h[idx] = elu1(acc);
}

// ---------------- CSR build ----------------
__global__ void count_kernel(const int* __restrict__ dst, int E, int* __restrict__ cnt) {
    int i = blockIdx.x * blockDim.x + threadIdx.x;
    if (i < E) atomicAdd(&cnt[dst[i]], 1);
}

// one block per edge type; exclusive scan of counts into offsets
__global__ void scan4_kernel(const int* __restrict__ cnt_base, int* __restrict__ off_base, int E) {
    const int Ns[4] = { NP, NG, NM, NG };
    int t = blockIdx.x;
    const int* cnt = cnt_base + t * NP;
    int* off = off_base + t * (NP + 1);
    int N = Ns[t];

    __shared__ int wsum[32];
    __shared__ int carry_s;
    if (threadIdx.x == 0) carry_s = 0;
    __syncthreads();
    int lane = threadIdx.x & 31, wid = threadIdx.x >> 5;
    int nw = blockDim.x >> 5;

    for (int base = 0; base < N; base += blockDim.x) {
        int i = base + threadIdx.x;
        int v = (i < N) ? cnt[i] : 0;
        int x = v;
#pragma unroll
        for (int o = 1; o < 32; o <<= 1) { int tt = __shfl_up_sync(FULL, x, o); if (lane >= o) x += tt; }
        if (lane == 31) wsum[wid] = x;
        __syncthreads();
        if (wid == 0) {
            int w = (lane < nw) ? wsum[lane] : 0;
#pragma unroll
            for (int o = 1; o < 32; o <<= 1) { int tt = __shfl_up_sync(FULL, w, o); if (lane >= o) w += tt; }
            wsum[lane] = w;
        }
        __syncthreads();
        int incl = x + (wid > 0 ? wsum[wid - 1] : 0);
        int carry = carry_s;
        if (i < N) off[i] = carry + incl - v;       // exclusive
        __syncthreads();
        if (threadIdx.x == blockDim.x - 1) carry_s = carry + incl;
        __syncthreads();
    }
    if (threadIdx.x == 0) off[N] = E;
}

__global__ void fill_kernel(const int* __restrict__ src, const int* __restrict__ dst,
                            int E, int* __restrict__ cur, int* __restrict__ col) {
    int i = blockIdx.x * blockDim.x + threadIdx.x;
    if (i < E) {
        int p = atomicAdd(&cur[dst[i]], 1);
        col[p] = src[i];
    }
}

// ---------------- merged pull aggregation (mean), all 4 edge types ----------------
// one warp per dst node across ALL segments; lane holds elems [lane], [32+lane]
__global__ void pull_all_kernel(const float* __restrict__ hbuf,
                                float* __restrict__ agg) {
    int warp = (blockIdx.x * blockDim.x + threadIdx.x) >> 5;
    int lane = threadIdx.x & 31;
    if (warp >= NSEG) return;

    int t, n;
    if      (warp < A1) { t = 0; n = warp; }
    else if (warp < A2) { t = 1; n = warp - A1; }
    else if (warp < A3) { t = 2; n = warp - A2; }
    else                { t = 3; n = warp - A3; }

    const int srcoff_tab[4] = { OFF_GENE, OFF_PAT, OFF_GENE, OFF_GRP };
    const float* h_src = hbuf + srcoff_tab[t];
    const int* off = g_off[t];
    const int* col = g_col[t];

    int o0 = off[n], o1 = off[n + 1];
    float acc0 = 0.f, acc1 = 0.f;
    for (int base = o0; base < o1; base += 32) {
        int idx = (base + lane < o1) ? col[base + lane] : 0;
        int m = min(32, o1 - base);
#pragma unroll 4
        for (int j = 0; j < m; j++) {
            int s = __shfl_sync(FULL, idx, j);
            const float* r = h_src + (size_t)s * HID;
            acc0 += __ldg(r + lane);
            acc1 += __ldg(r + 32 + lane);
        }
    }
    float inv = 1.f / fmaxf((float)(o1 - o0), 1.f);
    agg[(size_t)warp * HID + lane]      = acc0 * inv;
    agg[(size_t)warp * HID + 32 + lane] = acc1 * inv;
}

// ---------------- merged SAGE linear, all 4 edge types ----------------
// grid = TTOT blocks; each block owns a 64-node tile of one edge type.
// hn[seg + n,:] = agg[seg + n,:] @ Wl_t + bl_t + h_root[n,:] @ Wr_t
// dynamic smem: sWl[4096] | sWr[4096] | sA[4096] | sR[4096]  (64 KB)
__global__ void linear_all_kernel(const float* __restrict__ agg,
                                  const float* __restrict__ hbuf,
                                  const float* __restrict__ convWl,  // layer base [4,64,64]
                                  const float* __restrict__ convbl,  // layer base [4,64]
                                  const float* __restrict__ convWr,
                                  float* __restrict__ hn) {
    extern __shared__ float sm[];
    float* sWl = sm;
    float* sWr = sm + 4096;
    float* sA  = sm + 8192;
    float* sR  = sm + 12288;

    int b = blockIdx.x;
    int t, tile;
    if      (b < T0)            { t = 0; tile = b; }
    else if (b < T0 + T1)       { t = 1; tile = b - T0; }
    else if (b < T0 + T1 + T2)  { t = 2; tile = b - T0 - T1; }
    else                        { t = 3; tile = b - T0 - T1 - T2; }

    const int Ns_tab[4]      = { NP, NG, NM, NG };
    const int segoff_tab[4]  = { A0, A1, A2, A3 };
    const int rootoff_tab[4] = { OFF_PAT, OFF_GENE, OFF_GRP, OFF_GENE };
    const int N = Ns_tab[t];
    const int seg = segoff_tab[t];
    const float* h_root = hbuf + rootoff_tab[t];
    const float* Wl = convWl + (size_t)t * HID * HID;
    const float* bl = convbl + (size_t)t * HID;
    const float* Wr = convWr + (size_t)t * HID * HID;

    for (int i = threadIdx.x; i < 4096; i += 256) {
        sWl[i] = Wl[i];
        sWr[i] = Wr[i];
    }
    int tx = threadIdx.x & 15;   // col group: j0 = tx*4
    int ty = threadIdx.x >> 4;   // node group: nb = ty*4
    int j0 = tx * 4;
    int nb = ty * 4;
    float4 bias = *(const float4*)(bl + j0);

    int n0 = tile * 64;
    // stage A and R tiles (float4 coalesced)
    for (int i = threadIdx.x; i < 64 * 16; i += 256) {
        int nn = i >> 4, q = i & 15;
        int n = n0 + nn;
        float4 va = make_float4(0.f, 0.f, 0.f, 0.f), vr = va;
        if (n < N) {
            va = ((const float4*)(agg    + (size_t)(seg + n) * HID))[q];
            vr = ((const float4*)(h_root + (size_t)n * HID))[q];
        }
        *(float4*)&sA[nn * 64 + q * 4] = va;
        *(float4*)&sR[nn * 64 + q * 4] = vr;
    }
    __syncthreads();

    float acc[4][4];
#pragma unroll
    for (int i = 0; i < 4; i++) {
        acc[i][0] = bias.x; acc[i][1] = bias.y; acc[i][2] = bias.z; acc[i][3] = bias.w;
    }
#pragma unroll 8
    for (int k = 0; k < 64; k++) {
        float4 wl = *(const float4*)&sWl[k * 64 + j0];
        float4 wr = *(const float4*)&sWr[k * 64 + j0];
#pragma unroll
        for (int i = 0; i < 4; i++) {
            float a = sA[(nb + i) * 64 + k];
            float r = sR[(nb + i) * 64 + k];
            acc[i][0] += a * wl.x + r * wr.x;
            acc[i][1] += a * wl.y + r * wr.y;
            acc[i][2] += a * wl.z + r * wr.z;
            acc[i][3] += a * wl.w + r * wr.w;
        }
    }
#pragma unroll
    for (int i = 0; i < 4; i++) {
        int n = n0 + nb + i;
        if (n < N)
            *(float4*)(hn + (size_t)(seg + n) * HID + j0) =
                make_float4(acc[i][0], acc[i][1], acc[i][2], acc[i][3]);
    }
}

// ---------------- residual + layernorm + elu over ALL node types ----------------
// gene hn = hn[e1] + hn[e3]; patient hn = hn[e0]; group hn = hn[e2]
__global__ void update_all_kernel(float* __restrict__ h,
                                  const float* __restrict__ hn,
                                  const float* __restrict__ lnG,   // [3,64] for this layer
                                  const float* __restrict__ lnB) {
    int warp = (blockIdx.x * blockDim.x + threadIdx.x) >> 5;
    int lane = threadIdx.x & 31;
    if (warp >= NTOT) return;
    size_t base = (size_t)warp * HID;
    int t;
    float d0, d1;
    if (warp < NG) {                       // gene
        t = 0;
        int n = warp;
        size_t b1 = (size_t)(A1 + n) * HID;
        size_t b3 = (size_t)(A3 + n) * HID;
        d0 = hn[b1 + lane]      + hn[b3 + lane];
        d1 = hn[b1 + 32 + lane] + hn[b3 + 32 + lane];
    } else if (warp < NG + NP) {           // patient
        t = 1;
        int n = warp - NG;
        size_t b0 = (size_t)(A0 + n) * HID;
        d0 = hn[b0 + lane];
        d1 = hn[b0 + 32 + lane];
    } else {                               // group
        t = 2;
        int n = warp - NG - NP;
        size_t b2 = (size_t)(A2 + n) * HID;
        d0 = hn[b2 + lane];
        d1 = hn[b2 + 32 + lane];
    }
    const float* gamma = lnG + t * HID;
    const float* beta  = lnB + t * HID;
    float a = h[base + lane]      + d0;
    float c = h[base + 32 + lane] + d1;
    float s = a + c;
#pragma unroll
    for (int o = 16; o; o >>= 1) s += __shfl_xor_sync(FULL, s, o);
    float mean = s * (1.f / 64.f);
    float da = a - mean, dc = c - mean;
    float vs = da * da + dc * dc;
#pragma unroll
    for (int o = 16; o; o >>= 1) vs += __shfl_xor_sync(FULL, vs, o);
    float rstd = rsqrtf(vs * (1.f / 64.f) + 1e-5f);
    h[base + lane]      = elu1(da * rstd * gamma[lane]      + beta[lane]);
    h[base + 32 + lane] = elu1(dc * rstd * gamma[32 + lane] + beta[32 + lane]);
}

// ---------------- cox head: one warp per patient ----------------
__global__ void cox_kernel(const float* __restrict__ h,
                           const float* __restrict__ W1,
                           const float* __restrict__ b1,
                           const float* __restrict__ W2,
                           const float* __restrict__ b2,
                           float* __restrict__ out, int N) {
    __shared__ float sW1[HID * 32];
    __shared__ float sb1[32];
    __shared__ float sW2[32];
    __shared__ float sb2;
    for (int i = threadIdx.x; i < HID * 32; i += blockDim.x) sW1[i] = W1[i];
    if (threadIdx.x < 32) { sb1[threadIdx.x] = b1[threadIdx.x]; sW2[threadIdx.x] = W2[threadIdx.x]; }
    if (threadIdx.x == 0) sb2 = b2[0];
    __syncthreads();

    int warp = (blockIdx.x * blockDim.x + threadIdx.x) >> 5;
    int lane = threadIdx.x & 31;
    if (warp >= N) return;
    size_t base = (size_t)warp * HID;
    float a = h[base + lane];
    float c = h[base + 32 + lane];
    float z = sb1[lane];
#pragma unroll
    for (int k = 0; k < 32; k++) {
        float hk = __shfl_sync(FULL, a, k);
        z += hk * sW1[k * 32 + lane];
    }
#pragma unroll
    for (int k = 0; k < 32; k++) {
        float hk = __shfl_sync(FULL, c, k);
        z += hk * sW1[(k + 32) * 32 + lane];
    }
    z = elu1(z);
    float hz = z * sW2[lane];
#pragma unroll
    for (int o = 16; o; o >>= 1) hz += __shfl_xor_sync(FULL, hz, o);
    if (lane == 0) out[warp] = hz + sb2;
}

// ---------------- host launcher ----------------
static inline int cdiv(long long a, long long b) { return (int)((a + b - 1) / b); }

extern "C" void kernel_launch(void* const* d_in, const int* in_sizes, int n_in,
                              void* d_out, int out_size) {
    const float* x_gene = (const float*)d_in[0];
    const float* x_pat  = (const float*)d_in[1];
    const float* x_grp  = (const float*)d_in[2];
    const int* src[4] = { (const int*)d_in[3], (const int*)d_in[5],
                          (const int*)d_in[7], (const int*)d_in[9] };
    const int* dst[4] = { (const int*)d_in[4], (const int*)d_in[6],
                          (const int*)d_in[8], (const int*)d_in[10] };
    const float* encGW = (const float*)d_in[11];
    const float* encGb = (const float*)d_in[12];
    const float* encPW = (const float*)d_in[13];
    const float* encPb = (const float*)d_in[14];
    const float* encMW = (const float*)d_in[15];
    const float* encMb = (const float*)d_in[16];
    const float* convWl = (const float*)d_in[17];   // [2,4,64,64]
    const float* convbl = (const float*)d_in[18];   // [2,4,64]
    const float* convWr = (const float*)d_in[19];   // [2,4,64,64]
    const float* lnG = (const float*)d_in[20];      // [2,3,64]
    const float* lnB = (const float*)d_in[21];
    const float* coxW1 = (const float*)d_in[22];
    const float* coxb1 = (const float*)d_in[23];
    const float* coxW2 = (const float*)d_in[24];
    const float* coxb2 = (const float*)d_in[25];
    float* out = (float*)d_out;

    const int E = in_sizes[3];

    float *hbuf, *aggbuf, *hnbuf;
    int *cntb, *offb, *curb, *colb;
    cudaGetSymbolAddress((void**)&hbuf,   g_h);
    cudaGetSymbolAddress((void**)&aggbuf, g_agg);
    cudaGetSymbolAddress((void**)&hnbuf,  g_hn);
    cudaGetSymbolAddress((void**)&cntb,   g_cnt);
    cudaGetSymbolAddress((void**)&offb,   g_off);
    cudaGetSymbolAddress((void**)&curb,   g_cur);
    cudaGetSymbolAddress((void**)&colb,   g_col);

    float* h_gene = hbuf + OFF_GENE;
    float* h_pat  = hbuf + OFF_PAT;
    float* h_grp  = hbuf + OFF_GRP;

    static const int LIN_SMEM = 4 * 4096 * (int)sizeof(float);   // 64 KB
    cudaFuncSetAttribute(linear_all_kernel,
                         cudaFuncAttributeMaxDynamicSharedMemorySize, LIN_SMEM);

    // ---- encoders ----
    encoder_kernel<11><<<cdiv((long long)NG * HID, 256), 256>>>(x_gene, encGW, encGb, h_gene, NG);
    encoder_kernel<3> <<<cdiv((long long)NP * HID, 256), 256>>>(x_pat,  encPW, encPb, h_pat,  NP);
    encoder_kernel<4> <<<cdiv((long long)NM * HID, 256), 256>>>(x_grp,  encMW, encMb, h_grp,  NM);

    // ---- CSR build (topology fixed; reused by both layers) ----
    zero_int_kernel<<<256, 256>>>(cntb, 4 * NP);
    for (int e = 0; e < 4; e++)
        count_kernel<<<cdiv(E, 256), 256>>>(dst[e], E, cntb + e * NP);
    scan4_kernel<<<4, 1024>>>(cntb, offb, E);
    copy_int_kernel<<<256, 256>>>(curb, offb, 4 * (NP + 1));
    for (int e = 0; e < 4; e++)
        fill_kernel<<<cdiv(E, 256), 256>>>(src[e], dst[e], E, curb + e * (NP + 1), colb + (size_t)e * EMAX);

    // ---- layers: 3 launches each ----
    for (int layer = 0; layer < NLAYERS; layer++) {
        pull_all_kernel<<<cdiv((long long)NSEG * 32, 256), 256>>>(hbuf, aggbuf);
        linear_all_kernel<<<TTOT, 256, LIN_SMEM>>>(
            aggbuf, hbuf,
            convWl + (size_t)layer * 4 * HID * HID,
            convbl + (size_t)layer * 4 * HID,
            convWr + (size_t)layer * 4 * HID * HID,
            hnbuf);
        update_all_kernel<<<cdiv((long long)NTOT * 32, 256), 256>>>(
            hbuf, hnbuf, lnG + (size_t)layer * 3 * HID, lnB + (size_t)layer * 3 * HID);
    }

    // ---- cox head ----
    cox_kernel<<<cdiv((long long)NP * 32, 256), 256>>>(h_pat, coxW1, coxb1, coxW2, coxb2, out, NP);
}

// round 9
// speedup vs baseline: 1.9720x; 1.1203x over previous
#include <cuda_runtime.h>
#include <cuda_bf16.h>
#include <math.h>

#define NG 20000
#define NP 100000
#define NM 5000
#define NTOT (NG + NP + NM)
#define HID 64
#define NLAYERS 2
#define EMAX 1000000
#define FULL 0xFFFFFFFFu

// segment layout for agg/hn (per edge type dst rows): e0|e1|e2|e3
#define A0 0
#define A1 NP
#define A2 (NP + NG)
#define A3 (NP + NG + NM)
#define NSEG (NP + NG + NM + NG)

// tiles per type for the merged linear
#define T0 ((NP + 63) / 64)
#define T1 ((NG + 63) / 64)
#define T2 ((NM + 63) / 64)
#define T3 ((NG + 63) / 64)
#define TTOT (T0 + T1 + T2 + T3)

// scan chunking
#define SCH 1024
#define NB0 ((NP + SCH - 1) / SCH)   // 98
#define NB1 ((NG + SCH - 1) / SCH)   // 20
#define NB2 ((NM + SCH - 1) / SCH)   // 5
#define NB3 NB1                      // 20
#define NBTOT (NB0 + NB1 + NB2 + NB3)

// ---------------- scratch (static device globals; no allocs) ----------------
__device__ float g_h  [NTOT * HID];      // packed [gene | patient | group]
__device__ float g_agg[NSEG * HID];      // per-edge-type aggregated means
__device__ float g_hn [NSEG * HID];      // per-edge-type linear outputs
__device__ int   g_cnt[4][NP];           // per-type dst counts
__device__ int   g_off[4][NP + 1];       // CSR offsets
__device__ int   g_cur[4][NP + 1];       // fill cursors
__device__ int   g_col[4][EMAX];         // CSR column (src) indices
__device__ int   g_part[NBTOT];          // scan partial sums

#define OFF_GENE 0
#define OFF_PAT  (NG * HID)
#define OFF_GRP  ((NG + NP) * HID)

__device__ __forceinline__ float elu1(float x) { return x > 0.f ? x : expm1f(x); }

__device__ __forceinline__ void decode_scan_block(int b, int& t, int& c) {
    if      (b < NB0)             { t = 0; c = b; }
    else if (b < NB0 + NB1)       { t = 1; c = b - NB0; }
    else if (b < NB0 + NB1 + NB2) { t = 2; c = b - NB0 - NB1; }
    else                          { t = 3; c = b - NB0 - NB1 - NB2; }
}

__constant__ int c_Ns[4] = { NP, NG, NM, NG };

// ---------------- utility kernels ----------------
__global__ void zero_int_kernel(int* p, int n) {
    int i = blockIdx.x * blockDim.x + threadIdx.x;
    int stride = gridDim.x * blockDim.x;
    for (; i < n; i += stride) p[i] = 0;
}

// encoder: h[n,j] = elu(b[j] + sum_k x[n,k] * W[k,j])
template <int K>
__global__ void encoder_kernel(const float* __restrict__ x,
                               const float* __restrict__ W,
                               const float* __restrict__ b,
                               float* __restrict__ h, int N) {
    int idx = blockIdx.x * blockDim.x + threadIdx.x;
    if (idx >= N * HID) return;
    int n = idx >> 6;
    int j = idx & 63;
    float acc = b[j];
#pragma unroll
    for (int k = 0; k < K; k++)
        acc += x[n * K + k] * W[k * HID + j];
    h[idx] = elu1(acc);
}

// ---------------- CSR build ----------------
// merged degree count over all 4 edge types
__global__ void count_all_kernel(const int* __restrict__ d0, const int* __restrict__ d1,
                                 const int* __restrict__ d2, const int* __restrict__ d3,
                                 int E, int* __restrict__ cnt) {
    int i = blockIdx.x * blockDim.x + threadIdx.x;
    if (i >= 4 * E) return;
    int t = (i >= E) + (i >= 2 * E) + (i >= 3 * E);
    int j = i - t * E;
    const int* d = (t == 0) ? d0 : (t == 1) ? d1 : (t == 2) ? d2 : d3;
    atomicAdd(&cnt[t * NP + d[j]], 1);
}

// scan phase A: per-chunk partial sums (grid = NBTOT, 256 threads, 4 elems/thread)
__global__ void scanA_kernel() {
    int t, c;
    decode_scan_block(blockIdx.x, t, c);
    int N = c_Ns[t];
    const int* cnt = g_cnt[t];
    int base = c * SCH + threadIdx.x * 4;
    int s = 0;
#pragma unroll
    for (int k = 0; k < 4; k++) {
        int i = base + k;
        if (i < N) s += cnt[i];
    }
    __shared__ int wsum[8];
    int lane = threadIdx.x & 31, wid = threadIdx.x >> 5;
#pragma unroll
    for (int o = 16; o; o >>= 1) s += __shfl_xor_sync(FULL, s, o);
    if (lane == 0) wsum[wid] = s;
    __syncthreads();
    if (threadIdx.x == 0) {
        int tot = 0;
#pragma unroll
        for (int w = 0; w < 8; w++) tot += wsum[w];
        g_part[blockIdx.x] = tot;
    }
}

// scan phase B: exclusive scan of partials with per-type reset (1 block)
__global__ void scanB_kernel() {
    __shared__ int sp[NBTOT];
    if (threadIdx.x < NBTOT) sp[threadIdx.x] = g_part[threadIdx.x];
    __syncthreads();
    if (threadIdx.x == 0) {
        const int pb[5] = { 0, NB0, NB0 + NB1, NB0 + NB1 + NB2, NBTOT };
        for (int t = 0; t < 4; t++) {
            int run = 0;
            for (int i = pb[t]; i < pb[t + 1]; i++) {
                int v = sp[i];
                sp[i] = run;
                run += v;
            }
        }
    }
    __syncthreads();
    if (threadIdx.x < NBTOT) g_part[threadIdx.x] = sp[threadIdx.x];
}

// scan phase C: per-chunk exclusive scan + carry; writes off AND cur
__global__ void scanC_kernel(int E) {
    int t, c;
    decode_scan_block(blockIdx.x, t, c);
    int N = c_Ns[t];
    const int* cnt = g_cnt[t];
    int* off = g_off[t];
    int* cur = g_cur[t];
    int carry = g_part[blockIdx.x];

    int base = c * SCH + threadIdx.x * 4;
    int v[4];
    int tsum = 0;
#pragma unroll
    for (int k = 0; k < 4; k++) {
        int i = base + k;
        v[k] = (i < N) ? cnt[i] : 0;
        tsum += v[k];
    }
    // block exclusive scan of tsum over 256 threads
    __shared__ int wsum[8];
    int lane = threadIdx.x & 31, wid = threadIdx.x >> 5;
    int x = tsum;
#pragma unroll
    for (int o = 1; o < 32; o <<= 1) { int tt = __shfl_up_sync(FULL, x, o); if (lane >= o) x += tt; }
    if (lane == 31) wsum[wid] = x;
    __syncthreads();
    if (wid == 0 && lane < 8) {
        int w = wsum[lane];
#pragma unroll
        for (int o = 1; o < 8; o <<= 1) { int tt = __shfl_up_sync(0xFFu, w, o); if (lane >= o) w += tt; }
        wsum[lane] = w;
    }
    __syncthreads();
    int excl = (x - tsum) + (wid > 0 ? wsum[wid - 1] : 0) + carry;
#pragma unroll
    for (int k = 0; k < 4; k++) {
        int i = base + k;
        if (i < N) { off[i] = excl; cur[i] = excl; }
        excl += v[k];
    }
    // last block of each type writes the terminator
    if (threadIdx.x == 0 && c == (N + SCH - 1) / SCH - 1) off[N] = E;
}

// merged CSR fill over all 4 edge types
__global__ void fill_all_kernel(const int* __restrict__ s0, const int* __restrict__ d0,
                                const int* __restrict__ s1, const int* __restrict__ d1,
                                const int* __restrict__ s2, const int* __restrict__ d2,
                                const int* __restrict__ s3, const int* __restrict__ d3,
                                int E) {
    int i = blockIdx.x * blockDim.x + threadIdx.x;
    if (i >= 4 * E) return;
    int t = (i >= E) + (i >= 2 * E) + (i >= 3 * E);
    int j = i - t * E;
    const int* s = (t == 0) ? s0 : (t == 1) ? s1 : (t == 2) ? s2 : s3;
    const int* d = (t == 0) ? d0 : (t == 1) ? d1 : (t == 2) ? d2 : d3;
    int p = atomicAdd(&g_cur[t][d[j]], 1);
    g_col[t][p] = s[j];
}

// ---------------- merged pull aggregation (mean), float4 gather ----------------
// one warp per dst node; half-warps gather alternating neighbors, float4/lane
__global__ void pull_all_kernel(const float* __restrict__ hbuf,
                                float* __restrict__ agg) {
    int warp = (blockIdx.x * blockDim.x + threadIdx.x) >> 5;
    int lane = threadIdx.x & 31;
    if (warp >= NSEG) return;

    int t, n;
    if      (warp < A1) { t = 0; n = warp; }
    else if (warp < A2) { t = 1; n = warp - A1; }
    else if (warp < A3) { t = 2; n = warp - A2; }
    else                { t = 3; n = warp - A3; }

    const int srcoff_tab[4] = { OFF_GENE, OFF_PAT, OFF_GENE, OFF_GRP };
    const float* h_src = hbuf + srcoff_tab[t];
    const int* off = g_off[t];
    const int* col = g_col[t];

    const int half = lane >> 4;   // 0 or 1
    const int q    = lane & 15;   // float4 slot within 256B row

    int o0 = off[n], o1 = off[n + 1];
    float4 acc = make_float4(0.f, 0.f, 0.f, 0.f);
    for (int base = o0; base < o1; base += 32) {
        int idx = (base + lane < o1) ? col[base + lane] : 0;
        int m = min(32, o1 - base);
#pragma unroll 4
        for (int j = 0; j < m; j += 2) {
            int jj = j + half;
            int s = __shfl_sync(FULL, idx, jj & 31);
            if (jj < m) {
                float4 v = ((const float4*)(h_src + (size_t)s * HID))[q];
                acc.x += v.x; acc.y += v.y; acc.z += v.z; acc.w += v.w;
            }
        }
    }
    // combine the two halves
    acc.x += __shfl_xor_sync(FULL, acc.x, 16);
    acc.y += __shfl_xor_sync(FULL, acc.y, 16);
    acc.z += __shfl_xor_sync(FULL, acc.z, 16);
    acc.w += __shfl_xor_sync(FULL, acc.w, 16);
    if (half == 0) {
        float inv = 1.f / fmaxf((float)(o1 - o0), 1.f);
        *(float4*)&agg[(size_t)warp * HID + q * 4] =
            make_float4(acc.x * inv, acc.y * inv, acc.z * inv, acc.w * inv);
    }
}

// ---------------- merged SAGE linear, all 4 edge types ----------------
// grid = TTOT blocks; each block owns a 64-node tile of one edge type.
// dynamic smem: sWl[4096] | sWr[4096] | sA[4096] | sR[4096]  (64 KB)
__global__ void linear_all_kernel(const float* __restrict__ agg,
                                  const float* __restrict__ hbuf,
                                  const float* __restrict__ convWl,  // layer base [4,64,64]
                                  const float* __restrict__ convbl,  // layer base [4,64]
                                  const float* __restrict__ convWr,
                                  float* __restrict__ hn) {
    extern __shared__ float sm[];
    float* sWl = sm;
    float* sWr = sm + 4096;
    float* sA  = sm + 8192;
    float* sR  = sm + 12288;

    int b = blockIdx.x;
    int t, tile;
    if      (b < T0)            { t = 0; tile = b; }
    else if (b < T0 + T1)       { t = 1; tile = b - T0; }
    else if (b < T0 + T1 + T2)  { t = 2; tile = b - T0 - T1; }
    else                        { t = 3; tile = b - T0 - T1 - T2; }

    const int Ns_tab[4]      = { NP, NG, NM, NG };
    const int segoff_tab[4]  = { A0, A1, A2, A3 };
    const int rootoff_tab[4] = { OFF_PAT, OFF_GENE, OFF_GRP, OFF_GENE };
    const int N = Ns_tab[t];
    const int seg = segoff_tab[t];
    const float* h_root = hbuf + rootoff_tab[t];
    const float* Wl = convWl + (size_t)t * HID * HID;
    const float* bl = convbl + (size_t)t * HID;
    const float* Wr = convWr + (size_t)t * HID * HID;

    for (int i = threadIdx.x; i < 4096; i += 256) {
        sWl[i] = Wl[i];
        sWr[i] = Wr[i];
    }
    int tx = threadIdx.x & 15;   // col group: j0 = tx*4
    int ty = threadIdx.x >> 4;   // node group: nb = ty*4
    int j0 = tx * 4;
    int nb = ty * 4;
    float4 bias = *(const float4*)(bl + j0);

    int n0 = tile * 64;
    // stage A and R tiles (float4 coalesced)
    for (int i = threadIdx.x; i < 64 * 16; i += 256) {
        int nn = i >> 4, q = i & 15;
        int n = n0 + nn;
        float4 va = make_float4(0.f, 0.f, 0.f, 0.f), vr = va;
        if (n < N) {
            va = ((const float4*)(agg    + (size_t)(seg + n) * HID))[q];
            vr = ((const float4*)(h_root + (size_t)n * HID))[q];
        }
        *(float4*)&sA[nn * 64 + q * 4] = va;
        *(float4*)&sR[nn * 64 + q * 4] = vr;
    }
    __syncthreads();

    float acc[4][4];
#pragma unroll
    for (int i = 0; i < 4; i++) {
        acc[i][0] = bias.x; acc[i][1] = bias.y; acc[i][2] = bias.z; acc[i][3] = bias.w;
    }
#pragma unroll 8
    for (int k = 0; k < 64; k++) {
        float4 wl = *(const float4*)&sWl[k * 64 + j0];
        float4 wr = *(const float4*)&sWr[k * 64 + j0];
#pragma unroll
        for (int i = 0; i < 4; i++) {
            float a = sA[(nb + i) * 64 + k];
            float r = sR[(nb + i) * 64 + k];
            acc[i][0] += a * wl.x + r * wr.x;
            acc[i][1] += a * wl.y + r * wr.y;
            acc[i][2] += a * wl.z + r * wr.z;
            acc[i][3] += a * wl.w + r * wr.w;
        }
    }
#pragma unroll
    for (int i = 0; i < 4; i++) {
        int n = n0 + nb + i;
        if (n < N)
            *(float4*)(hn + (size_t)(seg + n) * HID + j0) =
                make_float4(acc[i][0], acc[i][1], acc[i][2], acc[i][3]);
    }
}

// ---------------- residual + layernorm + elu over ALL node types ----------------
// gene hn = hn[e1] + hn[e3]; patient hn = hn[e0]; group hn = hn[e2]
__global__ void update_all_kernel(float* __restrict__ h,
                                  const float* __restrict__ hn,
                                  const float* __restrict__ lnG,   // [3,64] for this layer
                                  const float* __restrict__ lnB) {
    int warp = (blockIdx.x * blockDim.x + threadIdx.x) >> 5;
    int lane = threadIdx.x & 31;
    if (warp >= NTOT) return;
    size_t base = (size_t)warp * HID;
    int t;
    float d0, d1;
    if (warp < NG) {                       // gene
        t = 0;
        int n = warp;
        size_t b1 = (size_t)(A1 + n) * HID;
        size_t b3 = (size_t)(A3 + n) * HID;
        d0 = hn[b1 + lane]      + hn[b3 + lane];
        d1 = hn[b1 + 32 + lane] + hn[b3 + 32 + lane];
    } else if (warp < NG + NP) {           // patient
        t = 1;
        int n = warp - NG;
        size_t b0 = (size_t)(A0 + n) * HID;
        d0 = hn[b0 + lane];
        d1 = hn[b0 + 32 + lane];
    } else {                               // group
        t = 2;
        int n = warp - NG - NP;
        size_t b2 = (size_t)(A2 + n) * HID;
        d0 = hn[b2 + lane];
        d1 = hn[b2 + 32 + lane];
    }
    const float* gamma = lnG + t * HID;
    const float* beta  = lnB + t * HID;
    float a = h[base + lane]      + d0;
    float c = h[base + 32 + lane] + d1;
    float s = a + c;
#pragma unroll
    for (int o = 16; o; o >>= 1) s += __shfl_xor_sync(FULL, s, o);
    float mean = s * (1.f / 64.f);
    float da = a - mean, dc = c - mean;
    float vs = da * da + dc * dc;
#pragma unroll
    for (int o = 16; o; o >>= 1) vs += __shfl_xor_sync(FULL, vs, o);
    float rstd = rsqrtf(vs * (1.f / 64.f) + 1e-5f);
    h[base + lane]      = elu1(da * rstd * gamma[lane]      + beta[lane]);
    h[base + 32 + lane] = elu1(dc * rstd * gamma[32 + lane] + beta[32 + lane]);
}

// ---------------- cox head: one warp per patient ----------------
__global__ void cox_kernel(const float* __restrict__ h,
                           const float* __restrict__ W1,
                           const float* __restrict__ b1,
                           const float* __restrict__ W2,
                           const float* __restrict__ b2,
                           float* __restrict__ out, int N) {
    __shared__ float sW1[HID * 32];
    __shared__ float sb1[32];
    __shared__ float sW2[32];
    __shared__ float sb2;
    for (int i = threadIdx.x; i < HID * 32; i += blockDim.x) sW1[i] = W1[i];
    if (threadIdx.x < 32) { sb1[threadIdx.x] = b1[threadIdx.x]; sW2[threadIdx.x] = W2[threadIdx.x]; }
    if (threadIdx.x == 0) sb2 = b2[0];
    __syncthreads();

    int warp = (blockIdx.x * blockDim.x + threadIdx.x) >> 5;
    int lane = threadIdx.x & 31;
    if (warp >= N) return;
    size_t base = (size_t)warp * HID;
    float a = h[base + lane];
    float c = h[base + 32 + lane];
    float z = sb1[lane];
#pragma unroll
    for (int k = 0; k < 32; k++) {
        float hk = __shfl_sync(FULL, a, k);
        z += hk * sW1[k * 32 + lane];
    }
#pragma unroll
    for (int k = 0; k < 32; k++) {
        float hk = __shfl_sync(FULL, c, k);
        z += hk * sW1[(k + 32) * 32 + lane];
    }
    z = elu1(z);
    float hz = z * sW2[lane];
#pragma unroll
    for (int o = 16; o; o >>= 1) hz += __shfl_xor_sync(FULL, hz, o);
    if (lane == 0) out[warp] = hz + sb2;
}

// ---------------- host launcher ----------------
static inline int cdiv(long long a, long long b) { return (int)((a + b - 1) / b); }

extern "C" void kernel_launch(void* const* d_in, const int* in_sizes, int n_in,
                              void* d_out, int out_size) {
    const float* x_gene = (const float*)d_in[0];
    const float* x_pat  = (const float*)d_in[1];
    const float* x_grp  = (const float*)d_in[2];
    const int* src0 = (const int*)d_in[3];
    const int* dst0 = (const int*)d_in[4];
    const int* src1 = (const int*)d_in[5];
    const int* dst1 = (const int*)d_in[6];
    const int* src2 = (const int*)d_in[7];
    const int* dst2 = (const int*)d_in[8];
    const int* src3 = (const int*)d_in[9];
    const int* dst3 = (const int*)d_in[10];
    const float* encGW = (const float*)d_in[11];
    const float* encGb = (const float*)d_in[12];
    const float* encPW = (const float*)d_in[13];
    const float* encPb = (const float*)d_in[14];
    const float* encMW = (const float*)d_in[15];
    const float* encMb = (const float*)d_in[16];
    const float* convWl = (const float*)d_in[17];   // [2,4,64,64]
    const float* convbl = (const float*)d_in[18];   // [2,4,64]
    const float* convWr = (const float*)d_in[19];   // [2,4,64,64]
    const float* lnG = (const float*)d_in[20];      // [2,3,64]
    const float* lnB = (const float*)d_in[21];
    const float* coxW1 = (const float*)d_in[22];
    const float* coxb1 = (const float*)d_in[23];
    const float* coxW2 = (const float*)d_in[24];
    const float* coxb2 = (const float*)d_in[25];
    float* out = (float*)d_out;

    const int E = in_sizes[3];

    float *hbuf, *aggbuf, *hnbuf;
    int *cntb;
    cudaGetSymbolAddress((void**)&hbuf,   g_h);
    cudaGetSymbolAddress((void**)&aggbuf, g_agg);
    cudaGetSymbolAddress((void**)&hnbuf,  g_hn);
    cudaGetSymbolAddress((void**)&cntb,   g_cnt);

    float* h_gene = hbuf + OFF_GENE;
    float* h_pat  = hbuf + OFF_PAT;
    float* h_grp  = hbuf + OFF_GRP;

    static const int LIN_SMEM = 4 * 4096 * (int)sizeof(float);   // 64 KB
    cudaFuncSetAttribute(linear_all_kernel,
                         cudaFuncAttributeMaxDynamicSharedMemorySize, LIN_SMEM);

    // ---- encoders ----
    encoder_kernel<11><<<cdiv((long long)NG * HID, 256), 256>>>(x_gene, encGW, encGb, h_gene, NG);
    encoder_kernel<3> <<<cdiv((long long)NP * HID, 256), 256>>>(x_pat,  encPW, encPb, h_pat,  NP);
    encoder_kernel<4> <<<cdiv((long long)NM * HID, 256), 256>>>(x_grp,  encMW, encMb, h_grp,  NM);

    // ---- CSR build (topology fixed; reused by both layers) ----
    zero_int_kernel<<<256, 256>>>(cntb, 4 * NP);
    count_all_kernel<<<cdiv(4LL * E, 256), 256>>>(dst0, dst1, dst2, dst3, E, cntb);
    scanA_kernel<<<NBTOT, 256>>>();
    scanB_kernel<<<1, 256>>>();
    scanC_kernel<<<NBTOT, 256>>>(E);
    fill_all_kernel<<<cdiv(4LL * E, 256), 256>>>(src0, dst0, src1, dst1,
                                                 src2, dst2, src3, dst3, E);

    // ---- layers: 3 launches each ----
    for (int layer = 0; layer < NLAYERS; layer++) {
        pull_all_kernel<<<cdiv((long long)NSEG * 32, 256), 256>>>(hbuf, aggbuf);
        linear_all_kernel<<<TTOT, 256, LIN_SMEM>>>(
            aggbuf, hbuf,
            convWl + (size_t)layer * 4 * HID * HID,
            convbl + (size_t)layer * 4 * HID,
            convWr + (size_t)layer * 4 * HID * HID,
            hnbuf);
        update_all_kernel<<<cdiv((long long)NTOT * 32, 256), 256>>>(
            hbuf, hnbuf, lnG + (size_t)layer * 3 * HID, lnB + (size_t)layer * 3 * HID);
    }

    // ---- cox head ----
    cox_kernel<<<cdiv((long long)NP * 32, 256), 256>>>(h_pat, coxW1, coxb1, coxW2, coxb2, out, NP);
}

// round 11
// speedup vs baseline: 2.0480x; 1.0385x over previous
#include <cuda_runtime.h>
#include <cuda_bf16.h>
#include <cuda_fp16.h>
#include <math.h>

#define NG 20000
#define NP 100000
#define NM 5000
#define NTOT (NG + NP + NM)
#define HID 64
#define NLAYERS 2
#define EMAX 1000000
#define FULL 0xFFFFFFFFu

// segment layout for agg/hn (per edge type dst rows): e0|e1|e2|e3
#define A0 0
#define A1 NP
#define A2 (NP + NG)
#define A3 (NP + NG + NM)
#define NSEG (NP + NG + NM + NG)

// tiles per type for the merged linear
#define T0 ((NP + 63) / 64)
#define T1 ((NG + 63) / 64)
#define T2 ((NM + 63) / 64)
#define T3 ((NG + 63) / 64)
#define TTOT (T0 + T1 + T2 + T3)

// scan chunking
#define SCH 1024
#define NB0 ((NP + SCH - 1) / SCH)   // 98
#define NB1 ((NG + SCH - 1) / SCH)   // 20
#define NB2 ((NM + SCH - 1) / SCH)   // 5
#define NB3 NB1                      // 20
#define NBTOT (NB0 + NB1 + NB2 + NB3)

// ---------------- scratch (static device globals; no allocs) ----------------
__device__ float  g_h  [NTOT * HID];      // fp32 master [gene | patient | group]
__device__ __align__(16) __half g_h16[NTOT * HID];  // fp16 gather mirror
__device__ float  g_agg[NSEG * HID];      // per-edge-type aggregated means
__device__ float  g_hn [NSEG * HID];      // per-edge-type linear outputs
__device__ int    g_cnt[4][NP];           // per-type dst counts
__device__ int    g_off[4][NP + 1];       // CSR offsets
__device__ int    g_cur[4][NP + 1];       // fill cursors
__device__ int    g_col[4][EMAX];         // CSR column (src) indices
__device__ int    g_part[NBTOT];          // scan partial sums

#define OFF_GENE 0
#define OFF_PAT  (NG * HID)
#define OFF_GRP  ((NG + NP) * HID)

__device__ __forceinline__ float elu1(float x) { return x > 0.f ? x : expm1f(x); }

__device__ __forceinline__ void decode_scan_block(int b, int& t, int& c) {
    if      (b < NB0)             { t = 0; c = b; }
    else if (b < NB0 + NB1)       { t = 1; c = b - NB0; }
    else if (b < NB0 + NB1 + NB2) { t = 2; c = b - NB0 - NB1; }
    else                          { t = 3; c = b - NB0 - NB1 - NB2; }
}

__constant__ int c_Ns[4] = { NP, NG, NM, NG };

// ---------------- utility kernels ----------------
__global__ void zero_int_kernel(int* p, int n) {
    int i = blockIdx.x * blockDim.x + threadIdx.x;
    int stride = gridDim.x * blockDim.x;
    for (; i < n; i += stride) p[i] = 0;
}

// encoder: h[n,j] = elu(b[j] + sum_k x[n,k] * W[k,j]); also writes fp16 mirror
template <int K>
__global__ void encoder_kernel(const float* __restrict__ x,
                               const float* __restrict__ W,
                               const float* __restrict__ b,
                               float* __restrict__ h,
                               __half* __restrict__ h16, int N) {
    int idx = blockIdx.x * blockDim.x + threadIdx.x;
    if (idx >= N * HID) return;
    int n = idx >> 6;
    int j = idx & 63;
    float acc = b[j];
#pragma unroll
    for (int k = 0; k < K; k++)
        acc += x[n * K + k] * W[k * HID + j];
    float y = elu1(acc);
    h[idx] = y;
    h16[idx] = __float2half(y);
}

// ---------------- CSR build ----------------
__global__ void count_all_kernel(const int* __restrict__ d0, const int* __restrict__ d1,
                                 const int* __restrict__ d2, const int* __restrict__ d3,
                                 int E, int* __restrict__ cnt) {
    int i = blockIdx.x * blockDim.x + threadIdx.x;
    if (i >= 4 * E) return;
    int t = (i >= E) + (i >= 2 * E) + (i >= 3 * E);
    int j = i - t * E;
    const int* d = (t == 0) ? d0 : (t == 1) ? d1 : (t == 2) ? d2 : d3;
    atomicAdd(&cnt[t * NP + d[j]], 1);
}

// scan phase A: per-chunk partial sums
__global__ void scanA_kernel() {
    int t, c;
    decode_scan_block(blockIdx.x, t, c);
    int N = c_Ns[t];
    const int* cnt = g_cnt[t];
    int base = c * SCH + threadIdx.x * 4;
    int s = 0;
#pragma unroll
    for (int k = 0; k < 4; k++) {
        int i = base + k;
        if (i < N) s += cnt[i];
    }
    __shared__ int wsum[8];
    int lane = threadIdx.x & 31, wid = threadIdx.x >> 5;
#pragma unroll
    for (int o = 16; o; o >>= 1) s += __shfl_xor_sync(FULL, s, o);
    if (lane == 0) wsum[wid] = s;
    __syncthreads();
    if (threadIdx.x == 0) {
        int tot = 0;
#pragma unroll
        for (int w = 0; w < 8; w++) tot += wsum[w];
        g_part[blockIdx.x] = tot;
    }
}

// scan phase B: exclusive scan of partials with per-type reset (1 block)
__global__ void scanB_kernel() {
    __shared__ int sp[NBTOT];
    if (threadIdx.x < NBTOT) sp[threadIdx.x] = g_part[threadIdx.x];
    __syncthreads();
    if (threadIdx.x == 0) {
        const int pb[5] = { 0, NB0, NB0 + NB1, NB0 + NB1 + NB2, NBTOT };
        for (int t = 0; t < 4; t++) {
            int run = 0;
            for (int i = pb[t]; i < pb[t + 1]; i++) {
                int v = sp[i];
                sp[i] = run;
                run += v;
            }
        }
    }
    __syncthreads();
    if (threadIdx.x < NBTOT) g_part[threadIdx.x] = sp[threadIdx.x];
}

// scan phase C: per-chunk exclusive scan + carry; writes off AND cur
__global__ void scanC_kernel(int E) {
    int t, c;
    decode_scan_block(blockIdx.x, t, c);
    int N = c_Ns[t];
    const int* cnt = g_cnt[t];
    int* off = g_off[t];
    int* cur = g_cur[t];
    int carry = g_part[blockIdx.x];

    int base = c * SCH + threadIdx.x * 4;
    int v[4];
    int tsum = 0;
#pragma unroll
    for (int k = 0; k < 4; k++) {
        int i = base + k;
        v[k] = (i < N) ? cnt[i] : 0;
        tsum += v[k];
    }
    __shared__ int wsum[8];
    int lane = threadIdx.x & 31, wid = threadIdx.x >> 5;
    int x = tsum;
#pragma unroll
    for (int o = 1; o < 32; o <<= 1) { int tt = __shfl_up_sync(FULL, x, o); if (lane >= o) x += tt; }
    if (lane == 31) wsum[wid] = x;
    __syncthreads();
    if (wid == 0 && lane < 8) {
        int w = wsum[lane];
#pragma unroll
        for (int o = 1; o < 8; o <<= 1) { int tt = __shfl_up_sync(0xFFu, w, o); if (lane >= o) w += tt; }
        wsum[lane] = w;
    }
    __syncthreads();
    int excl = (x - tsum) + (wid > 0 ? wsum[wid - 1] : 0) + carry;
#pragma unroll
    for (int k = 0; k < 4; k++) {
        int i = base + k;
        if (i < N) { off[i] = excl; cur[i] = excl; }
        excl += v[k];
    }
    if (threadIdx.x == 0 && c == (N + SCH - 1) / SCH - 1) off[N] = E;
}

// merged CSR fill over all 4 edge types
__global__ void fill_all_kernel(const int* __restrict__ s0, const int* __restrict__ d0,
                                const int* __restrict__ s1, const int* __restrict__ d1,
                                const int* __restrict__ s2, const int* __restrict__ d2,
                                const int* __restrict__ s3, const int* __restrict__ d3,
                                int E) {
    int i = blockIdx.x * blockDim.x + threadIdx.x;
    if (i >= 4 * E) return;
    int t = (i >= E) + (i >= 2 * E) + (i >= 3 * E);
    int j = i - t * E;
    const int* s = (t == 0) ? s0 : (t == 1) ? s1 : (t == 2) ? s2 : s3;
    const int* d = (t == 0) ? d0 : (t == 1) ? d1 : (t == 2) ? d2 : d3;
    int p = atomicAdd(&g_cur[t][d[j]], 1);
    g_col[t][p] = s[j];
}

// ---------------- merged pull aggregation (mean), fp16 gather ----------------
// one warp per dst node; quarter-warps gather 4 neighbors per LDG.128 step.
// 8 lanes cover a 128B fp16 row; accumulate fp32; write fp32 agg.
__global__ void pull_all_kernel(const __half* __restrict__ h16buf,
                                float* __restrict__ agg) {
    int warp = (blockIdx.x * blockDim.x + threadIdx.x) >> 5;
    int lane = threadIdx.x & 31;
    if (warp >= NSEG) return;

    int t, n;
    if      (warp < A1) { t = 0; n = warp; }
    else if (warp < A2) { t = 1; n = warp - A1; }
    else if (warp < A3) { t = 2; n = warp - A2; }
    else                { t = 3; n = warp - A3; }

    const int srcoff_tab[4] = { OFF_GENE, OFF_PAT, OFF_GENE, OFF_GRP };
    const __half* h_src = h16buf + srcoff_tab[t];
    const int* off = g_off[t];
    const int* col = g_col[t];

    const int qr = lane >> 3;   // quarter 0..3
    const int q8 = lane & 7;    // float4 slot within 128B fp16 row

    int o0 = off[n], o1 = off[n + 1];
    float2 acc[4];
#pragma unroll
    for (int k = 0; k < 4; k++) acc[k] = make_float2(0.f, 0.f);

    for (int base = o0; base < o1; base += 32) {
        int idx = (base + lane < o1) ? col[base + lane] : 0;
        int m = min(32, o1 - base);
#pragma unroll 4
        for (int j = 0; j < m; j += 4) {
            int jj = j + qr;
            int s = __shfl_sync(FULL, idx, jj & 31);
            if (jj < m) {
                float4 raw = ((const float4*)(h_src + (size_t)s * HID))[q8];
                const __half2* hp = (const __half2*)&raw;
#pragma unroll
                for (int k = 0; k < 4; k++) {
                    float2 f = __half22float2(hp[k]);
                    acc[k].x += f.x;
                    acc[k].y += f.y;
                }
            }
        }
    }
    // combine the four quarters
#pragma unroll
    for (int k = 0; k < 4; k++) {
        acc[k].x += __shfl_xor_sync(FULL, acc[k].x, 8);
        acc[k].y += __shfl_xor_sync(FULL, acc[k].y, 8);
        acc[k].x += __shfl_xor_sync(FULL, acc[k].x, 16);
        acc[k].y += __shfl_xor_sync(FULL, acc[k].y, 16);
    }
    if (qr == 0) {
        float inv = 1.f / fmaxf((float)(o1 - o0), 1.f);
        float4 w0 = make_float4(acc[0].x * inv, acc[0].y * inv, acc[1].x * inv, acc[1].y * inv);
        float4 w1 = make_float4(acc[2].x * inv, acc[2].y * inv, acc[3].x * inv, acc[3].y * inv);
        float4* dstp = (float4*)&agg[(size_t)warp * HID + q8 * 8];
        dstp[0] = w0;
        dstp[1] = w1;
    }
}

// ---------------- merged SAGE linear, all 4 edge types ----------------
// dynamic smem: sWl[4096] | sWr[4096] | sA[4096] | sR[4096]  (64 KB)
__global__ void linear_all_kernel(const float* __restrict__ agg,
                                  const float* __restrict__ hbuf,
                                  const float* __restrict__ convWl,  // layer base [4,64,64]
                                  const float* __restrict__ convbl,  // layer base [4,64]
                                  const float* __restrict__ convWr,
                                  float* __restrict__ hn) {
    extern __shared__ float sm[];
    float* sWl = sm;
    float* sWr = sm + 4096;
    float* sA  = sm + 8192;
    float* sR  = sm + 12288;

    int b = blockIdx.x;
    int t, tile;
    if      (b < T0)            { t = 0; tile = b; }
    else if (b < T0 + T1)       { t = 1; tile = b - T0; }
    else if (b < T0 + T1 + T2)  { t = 2; tile = b - T0 - T1; }
    else                        { t = 3; tile = b - T0 - T1 - T2; }

    const int Ns_tab[4]      = { NP, NG, NM, NG };
    const int segoff_tab[4]  = { A0, A1, A2, A3 };
    const int rootoff_tab[4] = { OFF_PAT, OFF_GENE, OFF_GRP, OFF_GENE };
    const int N = Ns_tab[t];
    const int seg = segoff_tab[t];
    const float* h_root = hbuf + rootoff_tab[t];
    const float* Wl = convWl + (size_t)t * HID * HID;
    const float* bl = convbl + (size_t)t * HID;
    const float* Wr = convWr + (size_t)t * HID * HID;

    for (int i = threadIdx.x; i < 4096; i += 256) {
        sWl[i] = Wl[i];
        sWr[i] = Wr[i];
    }
    int tx = threadIdx.x & 15;
    int ty = threadIdx.x >> 4;
    int j0 = tx * 4;
    int nb = ty * 4;
    float4 bias = *(const float4*)(bl + j0);

    int n0 = tile * 64;
    for (int i = threadIdx.x; i < 64 * 16; i += 256) {
        int nn = i >> 4, q = i & 15;
        int n = n0 + nn;
        float4 va = make_float4(0.f, 0.f, 0.f, 0.f), vr = va;
        if (n < N) {
            va = ((const float4*)(agg    + (size_t)(seg + n) * HID))[q];
            vr = ((const float4*)(h_root + (size_t)n * HID))[q];
        }
        *(float4*)&sA[nn * 64 + q * 4] = va;
        *(float4*)&sR[nn * 64 + q * 4] = vr;
    }
    __syncthreads();

    float acc[4][4];
#pragma unroll
    for (int i = 0; i < 4; i++) {
        acc[i][0] = bias.x; acc[i][1] = bias.y; acc[i][2] = bias.z; acc[i][3] = bias.w;
    }
#pragma unroll 8
    for (int k = 0; k < 64; k++) {
        float4 wl = *(const float4*)&sWl[k * 64 + j0];
        float4 wr = *(const float4*)&sWr[k * 64 + j0];
#pragma unroll
        for (int i = 0; i < 4; i++) {
            float a = sA[(nb + i) * 64 + k];
            float r = sR[(nb + i) * 64 + k];
            acc[i][0] += a * wl.x + r * wr.x;
            acc[i][1] += a * wl.y + r * wr.y;
            acc[i][2] += a * wl.z + r * wr.z;
            acc[i][3] += a * wl.w + r * wr.w;
        }
    }
#pragma unroll
    for (int i = 0; i < 4; i++) {
        int n = n0 + nb + i;
        if (n < N)
            *(float4*)(hn + (size_t)(seg + n) * HID + j0) =
                make_float4(acc[i][0], acc[i][1], acc[i][2], acc[i][3]);
    }
}

// ---------------- residual + layernorm + elu; writes fp32 h AND fp16 mirror ----------------
__global__ void update_all_kernel(float* __restrict__ h,
                                  __half* __restrict__ h16,
                                  const float* __restrict__ hn,
                                  const float* __restrict__ lnG,   // [3,64] for this layer
                                  const float* __restrict__ lnB) {
    int warp = (blockIdx.x * blockDim.x + threadIdx.x) >> 5;
    int lane = threadIdx.x & 31;
    if (warp >= NTOT) return;
    size_t base = (size_t)warp * HID;
    int t;
    float d0, d1;
    if (warp < NG) {                       // gene
        t = 0;
        int n = warp;
        size_t b1 = (size_t)(A1 + n) * HID;
        size_t b3 = (size_t)(A3 + n) * HID;
        d0 = hn[b1 + lane]      + hn[b3 + lane];
        d1 = hn[b1 + 32 + lane] + hn[b3 + 32 + lane];
    } else if (warp < NG + NP) {           // patient
        t = 1;
        int n = warp - NG;
        size_t b0 = (size_t)(A0 + n) * HID;
        d0 = hn[b0 + lane];
        d1 = hn[b0 + 32 + lane];
    } else {                               // group
        t = 2;
        int n = warp - NG - NP;
        size_t b2 = (size_t)(A2 + n) * HID;
        d0 = hn[b2 + lane];
        d1 = hn[b2 + 32 + lane];
    }
    const float* gamma = lnG + t * HID;
    const float* beta  = lnB + t * HID;
    float a = h[base + lane]      + d0;
    float c = h[base + 32 + lane] + d1;
    float s = a + c;
#pragma unroll
    for (int o = 16; o; o >>= 1) s += __shfl_xor_sync(FULL, s, o);
    float mean = s * (1.f / 64.f);
    float da = a - mean, dc = c - mean;
    float vs = da * da + dc * dc;
#pragma unroll
    for (int o = 16; o; o >>= 1) vs += __shfl_xor_sync(FULL, vs, o);
    float rstd = rsqrtf(vs * (1.f / 64.f) + 1e-5f);
    float y1 = elu1(da * rstd * gamma[lane]      + beta[lane]);
    float y2 = elu1(dc * rstd * gamma[32 + lane] + beta[32 + lane]);
    h[base + lane]        = y1;
    h[base + 32 + lane]   = y2;
    h16[base + lane]      = __float2half(y1);
    h16[base + 32 + lane] = __float2half(y2);
}

// ---------------- cox head: one warp per patient ----------------
__global__ void cox_kernel(const float* __restrict__ h,
                           const float* __restrict__ W1,
                           const float* __restrict__ b1,
                           const float* __restrict__ W2,
                           const float* __restrict__ b2,
                           float* __restrict__ out, int N) {
    __shared__ float sW1[HID * 32];
    __shared__ float sb1[32];
    __shared__ float sW2[32];
    __shared__ float sb2;
    for (int i = threadIdx.x; i < HID * 32; i += blockDim.x) sW1[i] = W1[i];
    if (threadIdx.x < 32) { sb1[threadIdx.x] = b1[threadIdx.x]; sW2[threadIdx.x] = W2[threadIdx.x]; }
    if (threadIdx.x == 0) sb2 = b2[0];
    __syncthreads();

    int warp = (blockIdx.x * blockDim.x + threadIdx.x) >> 5;
    int lane = threadIdx.x & 31;
    if (warp >= N) return;
    size_t base = (size_t)warp * HID;
    float a = h[base + lane];
    float c = h[base + 32 + lane];
    float z = sb1[lane];
#pragma unroll
    for (int k = 0; k < 32; k++) {
        float hk = __shfl_sync(FULL, a, k);
        z += hk * sW1[k * 32 + lane];
    }
#pragma unroll
    for (int k = 0; k < 32; k++) {
        float hk = __shfl_sync(FULL, c, k);
        z += hk * sW1[(k + 32) * 32 + lane];
    }
    z = elu1(z);
    float hz = z * sW2[lane];
#pragma unroll
    for (int o = 16; o; o >>= 1) hz += __shfl_xor_sync(FULL, hz, o);
    if (lane == 0) out[warp] = hz + sb2;
}

// ---------------- host launcher ----------------
static inline int cdiv(long long a, long long b) { return (int)((a + b - 1) / b); }

extern "C" void kernel_launch(void* const* d_in, const int* in_sizes, int n_in,
                              void* d_out, int out_size) {
    const float* x_gene = (const float*)d_in[0];
    const float* x_pat  = (const float*)d_in[1];
    const float* x_grp  = (const float*)d_in[2];
    const int* src0 = (const int*)d_in[3];
    const int* dst0 = (const int*)d_in[4];
    const int* src1 = (const int*)d_in[5];
    const int* dst1 = (const int*)d_in[6];
    const int* src2 = (const int*)d_in[7];
    const int* dst2 = (const int*)d_in[8];
    const int* src3 = (const int*)d_in[9];
    const int* dst3 = (const int*)d_in[10];
    const float* encGW = (const float*)d_in[11];
    const float* encGb = (const float*)d_in[12];
    const float* encPW = (const float*)d_in[13];
    const float* encPb = (const float*)d_in[14];
    const float* encMW = (const float*)d_in[15];
    const float* encMb = (const float*)d_in[16];
    const float* convWl = (const float*)d_in[17];   // [2,4,64,64]
    const float* convbl = (const float*)d_in[18];   // [2,4,64]
    const float* convWr = (const float*)d_in[19];   // [2,4,64,64]
    const float* lnG = (const float*)d_in[20];      // [2,3,64]
    const float* lnB = (const float*)d_in[21];
    const float* coxW1 = (const float*)d_in[22];
    const float* coxb1 = (const float*)d_in[23];
    const float* coxW2 = (const float*)d_in[24];
    const float* coxb2 = (const float*)d_in[25];
    float* out = (float*)d_out;

    const int E = in_sizes[3];

    float *hbuf, *aggbuf, *hnbuf;
    __half* h16buf;
    int *cntb;
    cudaGetSymbolAddress((void**)&hbuf,   g_h);
    cudaGetSymbolAddress((void**)&h16buf, g_h16);
    cudaGetSymbolAddress((void**)&aggbuf, g_agg);
    cudaGetSymbolAddress((void**)&hnbuf,  g_hn);
    cudaGetSymbolAddress((void**)&cntb,   g_cnt);

    float* h_gene = hbuf + OFF_GENE;
    float* h_pat  = hbuf + OFF_PAT;
    float* h_grp  = hbuf + OFF_GRP;

    static const int LIN_SMEM = 4 * 4096 * (int)sizeof(float);   // 64 KB
    cudaFuncSetAttribute(linear_all_kernel,
                         cudaFuncAttributeMaxDynamicSharedMemorySize, LIN_SMEM);

    // ---- encoders (write fp32 + fp16 mirror) ----
    encoder_kernel<11><<<cdiv((long long)NG * HID, 256), 256>>>(x_gene, encGW, encGb,
        h_gene, h16buf + OFF_GENE, NG);
    encoder_kernel<3> <<<cdiv((long long)NP * HID, 256), 256>>>(x_pat,  encPW, encPb,
        h_pat,  h16buf + OFF_PAT,  NP);
    encoder_kernel<4> <<<cdiv((long long)NM * HID, 256), 256>>>(x_grp,  encMW, encMb,
        h_grp,  h16buf + OFF_GRP,  NM);

    // ---- CSR build (topology fixed; reused by both layers) ----
    zero_int_kernel<<<256, 256>>>(cntb, 4 * NP);
    count_all_kernel<<<cdiv(4LL * E, 256), 256>>>(dst0, dst1, dst2, dst3, E, cntb);
    scanA_kernel<<<NBTOT, 256>>>();
    scanB_kernel<<<1, 256>>>();
    scanC_kernel<<<NBTOT, 256>>>(E);
    fill_all_kernel<<<cdiv(4LL * E, 256), 256>>>(src0, dst0, src1, dst1,
                                                 src2, dst2, src3, dst3, E);

    // ---- layers: 3 launches each ----
    for (int layer = 0; layer < NLAYERS; layer++) {
        pull_all_kernel<<<cdiv((long long)NSEG * 32, 256), 256>>>(h16buf, aggbuf);
        linear_all_kernel<<<TTOT, 256, LIN_SMEM>>>(
            aggbuf, hbuf,
            convWl + (size_t)layer * 4 * HID * HID,
            convbl + (size_t)layer * 4 * HID,
            convWr + (size_t)layer * 4 * HID * HID,
            hnbuf);
        update_all_kernel<<<cdiv((long long)NTOT * 32, 256), 256>>>(
            hbuf, h16buf, hnbuf,
            lnG + (size_t)layer * 3 * HID, lnB + (size_t)layer * 3 * HID);
    }

    // ---- cox head ----
    cox_kernel<<<cdiv((long long)NP * 32, 256), 256>>>(h_pat, coxW1, coxb1, coxW2, coxb2, out, NP);
}

// round 12
// speedup vs baseline: 2.6598x; 1.2988x over previous
#include <cuda_runtime.h>
#include <cuda_bf16.h>
#include <cuda_fp16.h>
#include <math.h>

#define NG 20000
#define NP 100000
#define NM 5000
#define NTOT (NG + NP + NM)
#define HID 64
#define EMAX 1000000
#define FULL 0xFFFFFFFFu

// live edge types (orig ids): 0: gene->patient, 1: patient->gene, 2(orig 3): group->gene
// segment layout for agg/hn: e0 | e1 | e3
#define A0 0
#define A1 NP
#define A3 (NP + NG)
#define NSEG1 (NP + 2 * NG)          // layer-1 pull covers all three
// tiles for the merged linear
#define T0 ((NP + 63) / 64)
#define T1 ((NG + 63) / 64)
#define T3 ((NG + 63) / 64)
#define TL1 (T0 + T1 + T3)
// scan chunking
#define SCH 1024
#define NB0 ((NP + SCH - 1) / SCH)   // 98
#define NB1 ((NG + SCH - 1) / SCH)   // 20
#define NB3 NB1                      // 20
#define NBTOT (NB0 + NB1 + NB3)      // 138

// ---------------- scratch (static device globals; no allocs) ----------------
__device__ float  g_h  [NTOT * HID];               // fp32 master [gene|patient|group]
__device__ __align__(16) __half g_h16[NTOT * HID]; // fp16 gather mirror
__device__ float  g_agg[NSEG1 * HID];
__device__ float  g_hn [NSEG1 * HID];
__device__ int    g_cnt[3][NP];      // zero at load; scanC restores zeros each call
__device__ int    g_off[3][NP + 1];
__device__ int    g_cur[3][NP + 1];
__device__ int    g_col[3][EMAX];
__device__ int    g_part[NBTOT];

#define OFF_GENE 0
#define OFF_PAT  (NG * HID)
#define OFF_GRP  ((NG + NP) * HID)

__device__ __forceinline__ float elu1(float x) { return x > 0.f ? x : expm1f(x); }

__constant__ int c_Ns[3] = { NP, NG, NG };

__device__ __forceinline__ void decode_scan_block(int b, int& t, int& c) {
    if      (b < NB0)       { t = 0; c = b; }
    else if (b < NB0 + NB1) { t = 1; c = b - NB0; }
    else                    { t = 2; c = b - NB0 - NB1; }
}

// ---------------- merged encoder: all 3 node types in one launch ----------------
// gene: K=11 (writes h + h16); patient: K=3 (h + h16); group: K=4 (h16 only)
__global__ void enc_all_kernel(const float* __restrict__ x_gene,
                               const float* __restrict__ x_pat,
                               const float* __restrict__ x_grp,
                               const float* __restrict__ Wg, const float* __restrict__ bg,
                               const float* __restrict__ Wp, const float* __restrict__ bp,
                               const float* __restrict__ Wm, const float* __restrict__ bm,
                               float* __restrict__ h, __half* __restrict__ h16) {
    int idx = blockIdx.x * blockDim.x + threadIdx.x;
    if (idx >= NTOT * HID) return;
    int n = idx >> 6;
    int j = idx & 63;
    const float* x; const float* W; const float* b; int K; int row; bool wf32;
    if (n < NG)           { x = x_gene; W = Wg; b = bg; K = 11; row = n;            wf32 = true; }
    else if (n < NG + NP) { x = x_pat;  W = Wp; b = bp; K = 3;  row = n - NG;       wf32 = true; }
    else                  { x = x_grp;  W = Wm; b = bm; K = 4;  row = n - NG - NP;  wf32 = false; }
    float acc = b[j];
    for (int k = 0; k < K; k++)
        acc += x[row * K + k] * W[k * HID + j];
    float y = elu1(acc);
    if (wf32) h[idx] = y;
    h16[idx] = __float2half(y);
}

// ---------------- CSR build (3 live edge types) ----------------
__global__ void count_all_kernel(const int* __restrict__ d0, const int* __restrict__ d1,
                                 const int* __restrict__ d3, int E) {
    int i = blockIdx.x * blockDim.x + threadIdx.x;
    if (i >= 3 * E) return;
    int t = (i >= E) + (i >= 2 * E);
    int j = i - t * E;
    const int* d = (t == 0) ? d0 : (t == 1) ? d1 : d3;
    atomicAdd(&g_cnt[t][d[j]], 1);
}

// scan phase A: per-chunk partial sums
__global__ void scanA_kernel() {
    int t, c;
    decode_scan_block(blockIdx.x, t, c);
    int N = c_Ns[t];
    const int* cnt = g_cnt[t];
    int base = c * SCH + threadIdx.x * 4;
    int s = 0;
#pragma unroll
    for (int k = 0; k < 4; k++) {
        int i = base + k;
        if (i < N) s += cnt[i];
    }
    __shared__ int wsum[8];
    int lane = threadIdx.x & 31, wid = threadIdx.x >> 5;
#pragma unroll
    for (int o = 16; o; o >>= 1) s += __shfl_xor_sync(FULL, s, o);
    if (lane == 0) wsum[wid] = s;
    __syncthreads();
    if (threadIdx.x == 0) {
        int tot = 0;
#pragma unroll
        for (int w = 0; w < 8; w++) tot += wsum[w];
        g_part[blockIdx.x] = tot;
    }
}

// scan phase C (with folded phase B): per-chunk exclusive scan with carry
// computed from predecessor partials; writes off AND cur; resets cnt to zero.
__global__ void scanC_kernel(int E) {
    int t, c;
    decode_scan_block(blockIdx.x, t, c);
    int N = c_Ns[t];
    int* cnt = g_cnt[t];
    int* off = g_off[t];
    int* cur = g_cur[t];

    // carry = sum of partials of preceding chunks of this type (warp 0)
    __shared__ int s_carry;
    int lane = threadIdx.x & 31, wid = threadIdx.x >> 5;
    if (wid == 0) {
        int pb = (t == 0) ? 0 : (t == 1) ? NB0 : NB0 + NB1;
        int sum = 0;
        for (int i = lane; i < c; i += 32) sum += g_part[pb + i];
#pragma unroll
        for (int o = 16; o; o >>= 1) sum += __shfl_xor_sync(FULL, sum, o);
        if (lane == 0) s_carry = sum;
    }
    __syncthreads();
    int carry = s_carry;

    int base = c * SCH + threadIdx.x * 4;
    int v[4];
    int tsum = 0;
#pragma unroll
    for (int k = 0; k < 4; k++) {
        int i = base + k;
        v[k] = (i < N) ? cnt[i] : 0;
        tsum += v[k];
    }
    __shared__ int wsum[8];
    int x = tsum;
#pragma unroll
    for (int o = 1; o < 32; o <<= 1) { int tt = __shfl_up_sync(FULL, x, o); if (lane >= o) x += tt; }
    if (lane == 31) wsum[wid] = x;
    __syncthreads();
    if (wid == 0 && lane < 8) {
        int w = wsum[lane];
#pragma unroll
        for (int o = 1; o < 8; o <<= 1) { int tt = __shfl_up_sync(0xFFu, w, o); if (lane >= o) w += tt; }
        wsum[lane] = w;
    }
    __syncthreads();
    int excl = (x - tsum) + (wid > 0 ? wsum[wid - 1] : 0) + carry;
#pragma unroll
    for (int k = 0; k < 4; k++) {
        int i = base + k;
        if (i < N) { off[i] = excl; cur[i] = excl; cnt[i] = 0; }  // restore zero invariant
        excl += v[k];
    }
    if (threadIdx.x == 0 && c == (N + SCH - 1) / SCH - 1) off[N] = E;
}

__global__ void fill_all_kernel(const int* __restrict__ s0, const int* __restrict__ d0,
                                const int* __restrict__ s1, const int* __restrict__ d1,
                                const int* __restrict__ s3, const int* __restrict__ d3,
                                int E) {
    int i = blockIdx.x * blockDim.x + threadIdx.x;
    if (i >= 3 * E) return;
    int t = (i >= E) + (i >= 2 * E);
    int j = i - t * E;
    const int* s = (t == 0) ? s0 : (t == 1) ? s1 : s3;
    const int* d = (t == 0) ? d0 : (t == 1) ? d1 : d3;
    int p = atomicAdd(&g_cur[t][d[j]], 1);
    g_col[t][p] = s[j];
}

// ---------------- pull aggregation (mean), fp16 gather ----------------
// one warp per dst node; quarter-warps gather 4 neighbors per LDG.128 step.
// nseg = NSEG1 (layer 1: e0,e1,e3) or NP (layer 2: e0 only).
__global__ void pull_all_kernel(const __half* __restrict__ h16buf,
                                float* __restrict__ agg, int nseg) {
    int warp = (blockIdx.x * blockDim.x + threadIdx.x) >> 5;
    int lane = threadIdx.x & 31;
    if (warp >= nseg) return;

    int t, n;
    if      (warp < A1) { t = 0; n = warp; }
    else if (warp < A3) { t = 1; n = warp - A1; }
    else                { t = 2; n = warp - A3; }

    const int srcoff_tab[3] = { OFF_GENE, OFF_PAT, OFF_GRP };
    const __half* h_src = h16buf + srcoff_tab[t];
    const int* off = g_off[t];
    const int* col = g_col[t];

    const int qr = lane >> 3;   // quarter 0..3
    const int q8 = lane & 7;    // float4 slot within 128B fp16 row

    int o0 = off[n], o1 = off[n + 1];
    float2 acc[4];
#pragma unroll
    for (int k = 0; k < 4; k++) acc[k] = make_float2(0.f, 0.f);

    for (int base = o0; base < o1; base += 32) {
        int idx = (base + lane < o1) ? col[base + lane] : 0;
        int m = min(32, o1 - base);
#pragma unroll 4
        for (int j = 0; j < m; j += 4) {
            int jj = j + qr;
            int s = __shfl_sync(FULL, idx, jj & 31);
            if (jj < m) {
                float4 raw = ((const float4*)(h_src + (size_t)s * HID))[q8];
                const __half2* hp = (const __half2*)&raw;
#pragma unroll
                for (int k = 0; k < 4; k++) {
                    float2 f = __half22float2(hp[k]);
                    acc[k].x += f.x;
                    acc[k].y += f.y;
                }
            }
        }
    }
#pragma unroll
    for (int k = 0; k < 4; k++) {
        acc[k].x += __shfl_xor_sync(FULL, acc[k].x, 8);
        acc[k].y += __shfl_xor_sync(FULL, acc[k].y, 8);
        acc[k].x += __shfl_xor_sync(FULL, acc[k].x, 16);
        acc[k].y += __shfl_xor_sync(FULL, acc[k].y, 16);
    }
    if (qr == 0) {
        float inv = 1.f / fmaxf((float)(o1 - o0), 1.f);
        float4 w0 = make_float4(acc[0].x * inv, acc[0].y * inv, acc[1].x * inv, acc[1].y * inv);
        float4 w1 = make_float4(acc[2].x * inv, acc[2].y * inv, acc[3].x * inv, acc[3].y * inv);
        float4* dstp = (float4*)&agg[(size_t)warp * HID + q8 * 8];
        dstp[0] = w0;
        dstp[1] = w1;
    }
}

// ---------------- merged SAGE linear ----------------
// layer 1 grid = TL1 (e0,e1,e3); layer 2 grid = T0 (e0 only).
// dynamic smem: sWl[4096] | sWr[4096] | sA[4096] | sR[4096]  (64 KB)
__global__ void linear_all_kernel(const float* __restrict__ agg,
                                  const float* __restrict__ hbuf,
                                  const float* __restrict__ convWl,  // layer base [4,64,64]
                                  const float* __restrict__ convbl,  // layer base [4,64]
                                  const float* __restrict__ convWr,
                                  float* __restrict__ hn) {
    extern __shared__ float sm[];
    float* sWl = sm;
    float* sWr = sm + 4096;
    float* sA  = sm + 8192;
    float* sR  = sm + 12288;

    int b = blockIdx.x;
    int t, tile;
    if      (b < T0)      { t = 0; tile = b; }
    else if (b < T0 + T1) { t = 1; tile = b - T0; }
    else                  { t = 2; tile = b - T0 - T1; }

    const int Ns_tab[3]      = { NP, NG, NG };
    const int segoff_tab[3]  = { A0, A1, A3 };
    const int rootoff_tab[3] = { OFF_PAT, OFF_GENE, OFF_GENE };
    const int orig_e_tab[3]  = { 0, 1, 3 };       // weight index in [4,...] arrays
    const int N = Ns_tab[t];
    const int seg = segoff_tab[t];
    const float* h_root = hbuf + rootoff_tab[t];
    const int oe = orig_e_tab[t];
    const float* Wl = convWl + (size_t)oe * HID * HID;
    const float* bl = convbl + (size_t)oe * HID;
    const float* Wr = convWr + (size_t)oe * HID * HID;

    for (int i = threadIdx.x; i < 4096; i += 256) {
        sWl[i] = Wl[i];
        sWr[i] = Wr[i];
    }
    int tx = threadIdx.x & 15;
    int ty = threadIdx.x >> 4;
    int j0 = tx * 4;
    int nb = ty * 4;
    float4 bias = *(const float4*)(bl + j0);

    int n0 = tile * 64;
    for (int i = threadIdx.x; i < 64 * 16; i += 256) {
        int nn = i >> 4, q = i & 15;
        int n = n0 + nn;
        float4 va = make_float4(0.f, 0.f, 0.f, 0.f), vr = va;
        if (n < N) {
            va = ((const float4*)(agg    + (size_t)(seg + n) * HID))[q];
            vr = ((const float4*)(h_root + (size_t)n * HID))[q];
        }
        *(float4*)&sA[nn * 64 + q * 4] = va;
        *(float4*)&sR[nn * 64 + q * 4] = vr;
    }
    __syncthreads();

    float acc[4][4];
#pragma unroll
    for (int i = 0; i < 4; i++) {
        acc[i][0] = bias.x; acc[i][1] = bias.y; acc[i][2] = bias.z; acc[i][3] = bias.w;
    }
#pragma unroll 8
    for (int k = 0; k < 64; k++) {
        float4 wl = *(const float4*)&sWl[k * 64 + j0];
        float4 wr = *(const float4*)&sWr[k * 64 + j0];
#pragma unroll
        for (int i = 0; i < 4; i++) {
            float a = sA[(nb + i) * 64 + k];
            float r = sR[(nb + i) * 64 + k];
            acc[i][0] += a * wl.x + r * wr.x;
            acc[i][1] += a * wl.y + r * wr.y;
            acc[i][2] += a * wl.z + r * wr.z;
            acc[i][3] += a * wl.w + r * wr.w;
        }
    }
#pragma unroll
    for (int i = 0; i < 4; i++) {
        int n = n0 + nb + i;
        if (n < N)
            *(float4*)(hn + (size_t)(seg + n) * HID + j0) =
                make_float4(acc[i][0], acc[i][1], acc[i][2], acc[i][3]);
    }
}

// ---------------- residual + layernorm + elu ----------------
// mode 0 (layer 1): gene (hn = A1+A3 segs; writes h16 only) + patient (hn = A0; writes fp32 only)
// mode 1 (layer 2): patient only (hn = A0; writes fp32 only)
__global__ void update_kernel(float* __restrict__ h,
                              __half* __restrict__ h16,
                              const float* __restrict__ hn,
                              const float* __restrict__ lnG,   // [3,64] layer base
                              const float* __restrict__ lnB,
                              int mode) {
    int warp = (blockIdx.x * blockDim.x + threadIdx.x) >> 5;
    int lane = threadIdx.x & 31;
    int nw = (mode == 0) ? (NG + NP) : NP;
    if (warp >= nw) return;

    int t;        // node-type index for LN params
    size_t base;  // h row base
    float d0, d1;
    bool wf32, wf16;
    if (mode == 0 && warp < NG) {          // gene
        t = 0;
        int n = warp;
        base = (size_t)n * HID;            // gene offset 0
        size_t b1 = (size_t)(A1 + n) * HID;
        size_t b3 = (size_t)(A3 + n) * HID;
        d0 = hn[b1 + lane]      + hn[b3 + lane];
        d1 = hn[b1 + 32 + lane] + hn[b3 + 32 + lane];
        wf32 = false; wf16 = true;         // only layer-2 e0 pull consumes gene
    } else {                               // patient
        t = 1;
        int n = (mode == 0) ? (warp - NG) : warp;
        base = (size_t)(NG + n) * HID;
        size_t b0 = (size_t)(A0 + n) * HID;
        d0 = hn[b0 + lane];
        d1 = hn[b0 + 32 + lane];
        wf32 = true; wf16 = false;         // linears/cox read fp32; no later fp16 pull of patient
    }
    const float* gamma = lnG + t * HID;
    const float* beta  = lnB + t * HID;
    float a = h[base + lane]      + d0;
    float c = h[base + 32 + lane] + d1;
    float s = a + c;
#pragma unroll
    for (int o = 16; o; o >>= 1) s += __shfl_xor_sync(FULL, s, o);
    float mean = s * (1.f / 64.f);
    float da = a - mean, dc = c - mean;
    float vs = da * da + dc * dc;
#pragma unroll
    for (int o = 16; o; o >>= 1) vs += __shfl_xor_sync(FULL, vs, o);
    float rstd = rsqrtf(vs * (1.f / 64.f) + 1e-5f);
    float y1 = elu1(da * rstd * gamma[lane]      + beta[lane]);
    float y2 = elu1(dc * rstd * gamma[32 + lane] + beta[32 + lane]);
    if (wf32) {
        h[base + lane]      = y1;
        h[base + 32 + lane] = y2;
    }
    if (wf16) {
        h16[base + lane]      = __float2half(y1);
        h16[base + 32 + lane] = __float2half(y2);
    }
}

// ---------------- cox head: one warp per patient ----------------
__global__ void cox_kernel(const float* __restrict__ h,
                           const float* __restrict__ W1,
                           const float* __restrict__ b1,
                           const float* __restrict__ W2,
                           const float* __restrict__ b2,
                           float* __restrict__ out, int N) {
    __shared__ float sW1[HID * 32];
    __shared__ float sb1[32];
    __shared__ float sW2[32];
    __shared__ float sb2;
    for (int i = threadIdx.x; i < HID * 32; i += blockDim.x) sW1[i] = W1[i];
    if (threadIdx.x < 32) { sb1[threadIdx.x] = b1[threadIdx.x]; sW2[threadIdx.x] = W2[threadIdx.x]; }
    if (threadIdx.x == 0) sb2 = b2[0];
    __syncthreads();

    int warp = (blockIdx.x * blockDim.x + threadIdx.x) >> 5;
    int lane = threadIdx.x & 31;
    if (warp >= N) return;
    size_t base = (size_t)warp * HID;
    float a = h[base + lane];
    float c = h[base + 32 + lane];
    float z = sb1[lane];
#pragma unroll
    for (int k = 0; k < 32; k++) {
        float hk = __shfl_sync(FULL, a, k);
        z += hk * sW1[k * 32 + lane];
    }
#pragma unroll
    for (int k = 0; k < 32; k++) {
        float hk = __shfl_sync(FULL, c, k);
        z += hk * sW1[(k + 32) * 32 + lane];
    }
    z = elu1(z);
    float hz = z * sW2[lane];
#pragma unroll
    for (int o = 16; o; o >>= 1) hz += __shfl_xor_sync(FULL, hz, o);
    if (lane == 0) out[warp] = hz + sb2;
}

// ---------------- host launcher ----------------
static inline int cdiv(long long a, long long b) { return (int)((a + b - 1) / b); }

extern "C" void kernel_launch(void* const* d_in, const int* in_sizes, int n_in,
                              void* d_out, int out_size) {
    const float* x_gene = (const float*)d_in[0];
    const float* x_pat  = (const float*)d_in[1];
    const float* x_grp  = (const float*)d_in[2];
    const int* src0 = (const int*)d_in[3];
    const int* dst0 = (const int*)d_in[4];
    const int* src1 = (const int*)d_in[5];
    const int* dst1 = (const int*)d_in[6];
    // d_in[7], d_in[8]: src2/dst2 (gene->mutation_group) — dead for the output
    const int* src3 = (const int*)d_in[9];
    const int* dst3 = (const int*)d_in[10];
    const float* encGW = (const float*)d_in[11];
    const float* encGb = (const float*)d_in[12];
    const float* encPW = (const float*)d_in[13];
    const float* encPb = (const float*)d_in[14];
    const float* encMW = (const float*)d_in[15];
    const float* encMb = (const float*)d_in[16];
    const float* convWl = (const float*)d_in[17];   // [2,4,64,64]
    const float* convbl = (const float*)d_in[18];   // [2,4,64]
    const float* convWr = (const float*)d_in[19];   // [2,4,64,64]
    const float* lnG = (const float*)d_in[20];      // [2,3,64]
    const float* lnB = (const float*)d_in[21];
    const float* coxW1 = (const float*)d_in[22];
    const float* coxb1 = (const float*)d_in[23];
    const float* coxW2 = (const float*)d_in[24];
    const float* coxb2 = (const float*)d_in[25];
    float* out = (float*)d_out;

    const int E = in_sizes[3];

    float *hbuf, *aggbuf, *hnbuf;
    __half* h16buf;
    cudaGetSymbolAddress((void**)&hbuf,   g_h);
    cudaGetSymbolAddress((void**)&h16buf, g_h16);
    cudaGetSymbolAddress((void**)&aggbuf, g_agg);
    cudaGetSymbolAddress((void**)&hnbuf,  g_hn);

    float* h_pat = hbuf + OFF_PAT;

    static const int LIN_SMEM = 4 * 4096 * (int)sizeof(float);   // 64 KB
    cudaFuncSetAttribute(linear_all_kernel,
                         cudaFuncAttributeMaxDynamicSharedMemorySize, LIN_SMEM);

    // [0] merged encoders
    enc_all_kernel<<<cdiv((long long)NTOT * HID, 256), 256>>>(
        x_gene, x_pat, x_grp, encGW, encGb, encPW, encPb, encMW, encMb,
        hbuf, h16buf);

    // [1-4] CSR build for live types {e0, e1, e3} (g_cnt zero by invariant)
    count_all_kernel<<<cdiv(3LL * E, 256), 256>>>(dst0, dst1, dst3, E);
    scanA_kernel<<<NBTOT, 256>>>();
    scanC_kernel<<<NBTOT, 256>>>(E);
    fill_all_kernel<<<cdiv(3LL * E, 256), 256>>>(src0, dst0, src1, dst1, src3, dst3, E);

    // ---- layer 1: e0, e1, e3 ----
    pull_all_kernel<<<cdiv((long long)NSEG1 * 32, 256), 256>>>(h16buf, aggbuf, NSEG1);
    linear_all_kernel<<<TL1, 256, LIN_SMEM>>>(
        aggbuf, hbuf, convWl, convbl, convWr, hnbuf);
    update_kernel<<<cdiv((long long)(NG + NP) * 32, 256), 256>>>(
        hbuf, h16buf, hnbuf, lnG, lnB, 0);

    // ---- layer 2: e0 only ----
    pull_all_kernel<<<cdiv((long long)NP * 32, 256), 256>>>(h16buf, aggbuf, NP);
    linear_all_kernel<<<T0, 256, LIN_SMEM>>>(
        aggbuf, hbuf,
        convWl + (size_t)4 * HID * HID,
        convbl + (size_t)4 * HID,
        convWr + (size_t)4 * HID * HID,
        hnbuf);
    update_kernel<<<cdiv((long long)NP * 32, 256), 256>>>(
        hbuf, h16buf, hnbuf, lnG + (size_t)3 * HID, lnB + (size_t)3 * HID, 1);

    // ---- cox head ----
    cox_kernel<<<cdiv((long long)NP * 32, 256), 256>>>(h_pat, coxW1, coxb1, coxW2, coxb2, out, NP);
}